// round 5
// baseline (speedup 1.0000x reference)
#include <cuda_runtime.h>
#include <cuda_bf16.h>
#include <math.h>
#include <stdint.h>

// ---------------- problem constants ----------------
#define BB   256      // batch
#define TT   128      // time steps
#define EE   1024     // input dim
#define HH   1024     // hidden dim
#define KP   3072     // logical split K' = 3*1024 (Ah*Bh + Ah*Bl + Al*Bh)
#define KP2  2048     // physical 2-segment layout [hi|lo]
#define EPSF 1e-6f

// ---------------- scratch (__device__ globals; no cudaMalloc) ----------------
__device__ __nv_bfloat16 g_Xs  [(size_t)BB * TT * KP2]; // X split [B*T, 2E] (hi|lo)
__device__ __nv_bfloat16 g_WihT[(size_t)HH * KP];       // W_ih^T [H, 3E] (hi|lo|hi)
__device__ __nv_bfloat16 g_WhhT[(size_t)HH * KP];       // W_hh^T [H, 3H] (hi|lo|hi)
__device__ __nv_bfloat16 g_hs  [(size_t)BB * KP2];      // h split [B, 2H] (hi|lo)
__device__ float g_prem[(size_t)BB * TT * HH];          // RAW X@W_ih (unscaled), all t
__device__ float g_mh  [4 * (size_t)BB * HH];           // 4 split-K partials of h @ W_hh
__device__ float g_xn  [(size_t)BB * TT];               // ||x_t|| per row (clamped)
__device__ unsigned g_bar_cnt = 0;
__device__ unsigned g_bar_gen = 0;

// logical chunk cg (0..47, 64 wide) -> physical A k-offset in [hi|lo] layout
// segments of 16 chunks: 0 -> hi, 1 -> hi, 2 -> lo
__device__ __forceinline__ int a_koff_seg(int cg) {
    return (((cg >> 4) == 2) ? 1024 : 0) + ((cg & 15) << 6);
}

// ---------------- small PTX helpers (sm_80-level, base-target safe) ----------
__device__ __forceinline__ uint32_t smem_u32(const void* p) {
    uint32_t a;
    asm("{ .reg .u64 t; cvta.to.shared.u64 t, %1; cvt.u32.u64 %0, t; }" : "=r"(a) : "l"(p));
    return a;
}
__device__ __forceinline__ void cpasync16(uint32_t s, const void* g) {
    asm volatile("cp.async.cg.shared.global [%0], [%1], 16;" :: "r"(s), "l"(g));
}
#define CP_COMMIT() asm volatile("cp.async.commit_group;" ::: "memory")
#define CP_WAIT1()  asm volatile("cp.async.wait_group 1;" ::: "memory")
#define CP_WAIT0()  asm volatile("cp.async.wait_group 0;" ::: "memory")

__device__ __forceinline__ void ldsm_x4(uint32_t& r0, uint32_t& r1, uint32_t& r2, uint32_t& r3,
                                        uint32_t addr) {
    asm volatile("ldmatrix.sync.aligned.m8n8.x4.shared.b16 {%0,%1,%2,%3}, [%4];"
                 : "=r"(r0), "=r"(r1), "=r"(r2), "=r"(r3) : "r"(addr));
}
__device__ __forceinline__ void mma_bf16(float& d0, float& d1, float& d2, float& d3,
                                         uint32_t a0, uint32_t a1, uint32_t a2, uint32_t a3,
                                         uint32_t b0, uint32_t b1) {
    asm volatile(
        "mma.sync.aligned.m16n8k16.row.col.f32.bf16.bf16.f32 "
        "{%0,%1,%2,%3}, {%4,%5,%6,%7}, {%8,%9}, {%0,%1,%2,%3};"
        : "+f"(d0), "+f"(d1), "+f"(d2), "+f"(d3)
        : "r"(a0), "r"(a1), "r"(a2), "r"(a3), "r"(b0), "r"(b1));
}

// ---------------- init ----------------
__global__ void init_kernel(uint32_t* hs_u32) {
    int i = blockIdx.x * blockDim.x + threadIdx.x;
    if (i < (int)((size_t)BB * KP2 / 2)) hs_u32[i] = 0u;
}

// ---------------- splitX: one block per row; also computes ||x|| -------------
__global__ __launch_bounds__(256) void splitX_kernel(const float* __restrict__ X,
                                                     __nv_bfloat16* __restrict__ Xs,
                                                     float* __restrict__ xn) {
    __shared__ float sh[8];
    size_t r = blockIdx.x;
    const float* x = X + r * EE;
    __nv_bfloat16* row = Xs + r * KP2;
    float x2 = 0.0f;
    #pragma unroll
    for (int j = 0; j < 4; j++) {
        int e = threadIdx.x + j * 256;
        float v = x[e];
        x2 += v * v;
        __nv_bfloat16 hi = __float2bfloat16(v);
        __nv_bfloat16 lo = __float2bfloat16(v - __bfloat162float(hi));
        row[e] = hi;
        row[EE + e] = lo;
    }
    #pragma unroll
    for (int o = 16; o > 0; o >>= 1) x2 += __shfl_down_sync(0xffffffffu, x2, o);
    if ((threadIdx.x & 31) == 0) sh[threadIdx.x >> 5] = x2;
    __syncthreads();
    if (threadIdx.x == 0) {
        float s = 0.0f;
        #pragma unroll
        for (int w = 0; w < 8; w++) s += sh[w];
        xn[r] = fmaxf(sqrtf(s), EPSF);
    }
}

// ---------------- W [K,N] fp32 -> Wt [N, 3K] bf16 (hi|lo|hi), transposed -----
__global__ __launch_bounds__(256) void splitWT_kernel(const float* __restrict__ W,
                                                      __nv_bfloat16* __restrict__ Wt) {
    __shared__ float tile[32][33];
    int n0 = blockIdx.x * 32;
    int k0 = blockIdx.y * 32;
    int tx = threadIdx.x & 31;
    int ty = threadIdx.x >> 5;
    #pragma unroll
    for (int i = 0; i < 32; i += 8)
        tile[ty + i][tx] = W[(size_t)(k0 + ty + i) * HH + n0 + tx];
    __syncthreads();
    #pragma unroll
    for (int i = 0; i < 32; i += 8) {
        float v = tile[tx][ty + i];
        int n = n0 + ty + i;
        int k = k0 + tx;
        __nv_bfloat16 hi = __float2bfloat16(v);
        __nv_bfloat16 lo = __float2bfloat16(v - __bfloat162float(hi));
        __nv_bfloat16* row = Wt + (size_t)n * KP;
        row[k] = hi;
        row[HH + k] = lo;
        row[2 * HH + k] = hi;
    }
}

// ---------------- big GEMM: prem_raw = Xs(2-seg) @ WihT^T ----------------
// BM=128, BN=128, 256 thr, 8 warps (2x4), 2-stage cp.async, 48 logical chunks.
__global__ void __launch_bounds__(256, 2)
big_gemm_kernel(const __nv_bfloat16* __restrict__ A,
                const __nv_bfloat16* __restrict__ B,
                float* __restrict__ C)
{
    constexpr int BM = 128, BN = 128;
    constexpr int ABYTES = BM * 128, BBYTES = BN * 128;
    extern __shared__ char smem[];
    uint32_t sbase = smem_u32(smem);
    uint32_t sA[2], sB[2];
    sA[0] = sbase;                   sB[0] = sbase + ABYTES;
    sA[1] = sbase + ABYTES + BBYTES; sB[1] = sA[1] + ABYTES;

    int tid  = threadIdx.x;
    int warp = tid >> 5;
    int lane = tid & 31;
    int wm = warp & 1;         // WARP_M = 64, MT = 4
    int wn = warp >> 1;        // WARP_N = 32, NT8 = 4, NX4 = 2

    size_t rowTile = (size_t)blockIdx.y * BM;
    size_t colTile = (size_t)blockIdx.x * BN;
    const __nv_bfloat16* Abase = A + rowTile * KP2;
    const __nv_bfloat16* Bbase = B + colTile * KP;

    float acc[4][4][4];
    #pragma unroll
    for (int i = 0; i < 4; i++)
        #pragma unroll
        for (int j = 0; j < 4; j++)
            #pragma unroll
            for (int e = 0; e < 4; e++) acc[i][j][e] = 0.0f;

    auto load_stage = [&](int st, int c) {
        const __nv_bfloat16* Ag = Abase + a_koff_seg(c);
        const __nv_bfloat16* Bg = Bbase + (size_t)c * 64;
        #pragma unroll
        for (int u = tid; u < BM * 8; u += 256) {
            int row = u >> 3, ch = u & 7;
            uint32_t phys = (uint32_t)(row * 128 + ((ch ^ (row & 7)) << 4));
            cpasync16(sA[st] + phys, Ag + (size_t)row * KP2 + ch * 8);
        }
        #pragma unroll
        for (int u = tid; u < BN * 8; u += 256) {
            int row = u >> 3, ch = u & 7;
            uint32_t phys = (uint32_t)(row * 128 + ((ch ^ (row & 7)) << 4));
            cpasync16(sB[st] + phys, Bg + (size_t)row * KP + ch * 8);
        }
    };

    load_stage(0, 0);
    CP_COMMIT();

    for (int c = 0; c < 48; c++) {
        if (c + 1 < 48) load_stage((c + 1) & 1, c + 1);
        CP_COMMIT();
        CP_WAIT1();
        __syncthreads();

        uint32_t a = sA[c & 1], b = sB[c & 1];
        #pragma unroll
        for (int s = 0; s < 4; s++) {
            uint32_t af[4][4];
            #pragma unroll
            for (int i = 0; i < 4; i++) {
                int row = wm * 64 + i * 16 + (lane & 15);
                int ch  = 2 * s + (lane >> 4);
                ldsm_x4(af[i][0], af[i][1], af[i][2], af[i][3],
                        a + row * 128 + ((ch ^ (row & 7)) << 4));
            }
            uint32_t bf[2][4];
            #pragma unroll
            for (int j = 0; j < 2; j++) {
                int row = wn * 32 + j * 16 + (lane & 7) + ((lane >> 4) << 3);
                int ch  = 2 * s + ((lane >> 3) & 1);
                ldsm_x4(bf[j][0], bf[j][1], bf[j][2], bf[j][3],
                        b + row * 128 + ((ch ^ (row & 7)) << 4));
            }
            #pragma unroll
            for (int i = 0; i < 4; i++)
                #pragma unroll
                for (int nj = 0; nj < 4; nj++)
                    mma_bf16(acc[i][nj][0], acc[i][nj][1], acc[i][nj][2], acc[i][nj][3],
                             af[i][0], af[i][1], af[i][2], af[i][3],
                             bf[nj >> 1][(nj & 1) * 2], bf[nj >> 1][(nj & 1) * 2 + 1]);
        }
        __syncthreads();
    }

    int g = lane >> 2, t4 = lane & 3;
    #pragma unroll
    for (int i = 0; i < 4; i++)
        #pragma unroll
        for (int nj = 0; nj < 4; nj++) {
            size_t row0 = rowTile + wm * 64 + i * 16 + g;
            size_t col  = colTile + wn * 32 + nj * 8 + 2 * t4;
            *reinterpret_cast<float2*>(&C[row0 * HH + col]) =
                make_float2(acc[i][nj][0], acc[i][nj][1]);
            *reinterpret_cast<float2*>(&C[(row0 + 8) * HH + col]) =
                make_float2(acc[i][nj][2], acc[i][nj][3]);
        }
}

// ---------------- helpers for step math ----------------
template <int NV>
__device__ __forceinline__ void block_reduce4(float* vals, float* shbuf /* NV*4 */) {
    __syncthreads();                 // guard reuse of shbuf
    #pragma unroll
    for (int v = 0; v < NV; v++) {
        float x = vals[v];
        #pragma unroll
        for (int o = 16; o > 0; o >>= 1) x += __shfl_down_sync(0xffffffffu, x, o);
        if ((threadIdx.x & 31) == 0) shbuf[v * 4 + (threadIdx.x >> 5)] = x;
    }
    __syncthreads();
    #pragma unroll
    for (int v = 0; v < NV; v++)
        vals[v] = shbuf[v * 4] + shbuf[v * 4 + 1] + shbuf[v * 4 + 2] + shbuf[v * 4 + 3];
}
__device__ __forceinline__ float artanh_clip(float x) {
    return atanhf(fminf(x, 1.0f - 1e-6f));
}

// ---------------- persistent recurrence kernel ----------------
// 128 CTAs x 128 threads, 1/SM.  CTA id -> z = K-quarter (768), x = col tile
// (128 wide), y = row tile (64 tall).  B tile (W_hh split) resident in SMEM.
#define PK_NCTA 128

__device__ __forceinline__ void grid_barrier() {
    __threadfence();
    __syncthreads();
    if (threadIdx.x == 0) {
        unsigned gen = *(volatile unsigned*)&g_bar_gen;
        unsigned old = atomicAdd(&g_bar_cnt, 1u);
        if (old == PK_NCTA - 1) {
            g_bar_cnt = 0;
            __threadfence();
            atomicExch(&g_bar_gen, gen + 1);
        } else {
            while (*(volatile unsigned*)&g_bar_gen == gen) { __nanosleep(32); }
        }
        __threadfence();
    }
    __syncthreads();
}

__global__ void __launch_bounds__(128, 1)
recurrence_kernel(const __nv_bfloat16* __restrict__ W,  // WhhT [H, 3H]
                  const float* __restrict__ prem,       // raw [B,T,H]
                  const float* __restrict__ bvec,       // b_h
                  const float* __restrict__ xn_arr,     // [B*T]
                  __nv_bfloat16* __restrict__ hs,       // [B, 2H]
                  float* __restrict__ mh,               // [4][B][H]
                  float* __restrict__ out)              // [B,H]
{
    constexpr int BCH = 12;                 // 12 chunks of 64 = 768 K-quarter
    constexpr int CHB = 128 * 128;          // bytes per B chunk (128 rows x 128B)
    extern __shared__ char smem[];
    __shared__ float redbuf[6 * 4];
    uint32_t sbase = smem_u32(smem);
    uint32_t sBres = sbase;                 // 12 * 16KB = 192KB resident B
    uint32_t sA[2] = { sbase + BCH * CHB, sbase + BCH * CHB + 64 * 128 };

    int bid  = blockIdx.x;
    int z = bid & 3;                        // K quarter
    int x = (bid >> 2) & 7;                 // col tile (128 wide)
    int y = bid >> 5;                       // row tile (64 tall)
    int tid  = threadIdx.x;
    int warp = tid >> 5;
    int lane = tid & 31;
    int wm = warp & 1;                      // WARP_M = 32, MT = 2
    int wn = warp >> 1;                     // WARP_N = 64, NT8 = 8, NX4 = 4

    // ---- load resident B tile: rows [x*128, x*128+128) of W, K [z*768, +768)
    {
        const __nv_bfloat16* Wb = W + (size_t)(x * 128) * KP + (size_t)z * 768;
        for (int u = tid; u < BCH * 128 * 8; u += 128) {
            int c   = u / (128 * 8);
            int rem = u - c * (128 * 8);
            int row = rem >> 3, ch = rem & 7;
            uint32_t phys = (uint32_t)(c * CHB + row * 128 + ((ch ^ (row & 7)) << 4));
            cpasync16(sBres + phys, Wb + (size_t)row * KP + c * 64 + ch * 8);
        }
        CP_COMMIT();
    }

    const __nv_bfloat16* Abase = hs + (size_t)(y * 64) * KP2;
    float* mhz = mh + (size_t)z * BB * HH;

    float hn_loc[2] = { EPSF, EPSF };
    int b0 = bid * 2;                       // step-phase rows: b0, b0+1

    auto loadA = [&](int st, int c) {       // A chunk: 64 rows x 64 k
        int koff = a_koff_seg(z * BCH + c);
        #pragma unroll
        for (int u = tid; u < 64 * 8; u += 128) {
            int row = u >> 3, ch = u & 7;
            uint32_t phys = (uint32_t)(row * 128 + ((ch ^ (row & 7)) << 4));
            cpasync16(sA[st] + phys, Abase + (size_t)row * KP2 + koff + ch * 8);
        }
    };

    for (int t = 0; t < TT; t++) {
        // ================= GEMM phase: mh[z] tile = hs_tile @ Wres^T ==========
        float acc[2][8][4];
        #pragma unroll
        for (int i = 0; i < 2; i++)
            #pragma unroll
            for (int j = 0; j < 8; j++)
                #pragma unroll
                for (int e = 0; e < 4; e++) acc[i][j][e] = 0.0f;

        loadA(0, 0);
        CP_COMMIT();
        for (int c = 0; c < BCH; c++) {
            if (c + 1 < BCH) loadA((c + 1) & 1, c + 1);
            CP_COMMIT();
            CP_WAIT1();
            __syncthreads();

            uint32_t a = sA[c & 1];
            uint32_t b = sBres + c * CHB;
            #pragma unroll
            for (int s = 0; s < 4; s++) {
                uint32_t af[2][4];
                #pragma unroll
                for (int i = 0; i < 2; i++) {
                    int row = wm * 32 + i * 16 + (lane & 15);
                    int ch  = 2 * s + (lane >> 4);
                    ldsm_x4(af[i][0], af[i][1], af[i][2], af[i][3],
                            a + row * 128 + ((ch ^ (row & 7)) << 4));
                }
                uint32_t bf[4][4];
                #pragma unroll
                for (int j = 0; j < 4; j++) {
                    int row = wn * 64 + j * 16 + (lane & 7) + ((lane >> 4) << 3);
                    int ch  = 2 * s + ((lane >> 3) & 1);
                    ldsm_x4(bf[j][0], bf[j][1], bf[j][2], bf[j][3],
                            b + row * 128 + ((ch ^ (row & 7)) << 4));
                }
                #pragma unroll
                for (int i = 0; i < 2; i++)
                    #pragma unroll
                    for (int nj = 0; nj < 8; nj++)
                        mma_bf16(acc[i][nj][0], acc[i][nj][1], acc[i][nj][2], acc[i][nj][3],
                                 af[i][0], af[i][1], af[i][2], af[i][3],
                                 bf[nj >> 1][(nj & 1) * 2], bf[nj >> 1][(nj & 1) * 2 + 1]);
            }
            __syncthreads();
        }

        // epilogue -> mh[z]
        {
            int g = lane >> 2, t4 = lane & 3;
            #pragma unroll
            for (int i = 0; i < 2; i++)
                #pragma unroll
                for (int nj = 0; nj < 8; nj++) {
                    size_t row0 = (size_t)(y * 64 + wm * 32 + i * 16 + g);
                    size_t col  = (size_t)(x * 128 + wn * 64 + nj * 8 + 2 * t4);
                    *reinterpret_cast<float2*>(&mhz[row0 * HH + col]) =
                        make_float2(acc[i][nj][0], acc[i][nj][1]);
                    *reinterpret_cast<float2*>(&mhz[(row0 + 8) * HH + col]) =
                        make_float2(acc[i][nj][2], acc[i][nj][3]);
                }
        }
        grid_barrier();

        // ================= STEP phase: rows b0, b0+1 =========================
        for (int r = 0; r < 2; r++) {
            int b = b0 + r;
            const float* pr = prem + ((size_t)b * TT + t) * HH;
            float p[8], m[8], bv[8];
            float s_mx2 = 0, s_mxm = 0, s_mxb = 0, s_m2 = 0, s_mb = 0, s_b2 = 0;
            #pragma unroll
            for (int j = 0; j < 8; j++) {
                int e = tid + j * 128;
                float mv = __ldcv(&mh[(size_t)0 * BB * HH + (size_t)b * HH + e])
                         + __ldcv(&mh[(size_t)1 * BB * HH + (size_t)b * HH + e])
                         + __ldcv(&mh[(size_t)2 * BB * HH + (size_t)b * HH + e])
                         + __ldcv(&mh[(size_t)3 * BB * HH + (size_t)b * HH + e]);
                float pv = pr[e];
                float bb = bvec[e];
                m[j] = mv; p[j] = pv; bv[j] = bb;
                s_mx2 += pv * pv;  s_mxm += pv * mv;  s_mxb += pv * bb;
                s_m2  += mv * mv;  s_mb  += mv * bb;  s_b2  += bb * bb;
            }
            float vals[6] = { s_mx2, s_mxm, s_mxb, s_m2, s_mb, s_b2 };
            block_reduce4<6>(vals, redbuf);
            float mx2 = vals[0], mxm = vals[1], mxb = vals[2];
            float m2  = vals[3], mb  = vals[4], b2  = vals[5];

            // prem scaling (mobius_matvec on x_t) from raw mx
            float xn  = xn_arr[(size_t)b * TT + t];
            float mxn = fmaxf(sqrtf(mx2), EPSF);
            float fp  = tanhf(mxn / xn * artanh_clip(xn)) / mxn;
            float p2  = fp * fp * mx2;
            float pm  = fp * mxm;
            float pb  = fp * mxb;

            // u = mobius_matvec(h, W_hh) scale
            float hn  = hn_loc[r];
            float mhn = fmaxf(sqrtf(m2), EPSF);
            float fu  = tanhf(mhn / hn * artanh_clip(hn)) / mhn;
            float u2  = fu * fu * m2;
            float ub  = fu * mb;

            // hid = mobius_add(u, b) = a1*u + c1*b
            float den1 = fmaxf(1.0f + 2.0f * ub + u2 * b2, EPSF);
            float a1 = (1.0f + 2.0f * ub + b2) / den1;
            float c1 = (1.0f - u2) / den1;
            float hid2 = a1 * a1 * u2 + 2.0f * a1 * c1 * ub + c1 * c1 * b2;
            float ph   = a1 * fu * pm + c1 * pb;

            // s = mobius_add(p, hid) = q1*p + q2*hid
            float den2 = fmaxf(1.0f + 2.0f * ph + p2 * hid2, EPSF);
            float q1 = (1.0f + 2.0f * ph + hid2) / den2;
            float q2 = (1.0f - p2) / den2;
            float s2 = q1 * q1 * p2 + q2 * q2 * hid2 + 2.0f * q1 * q2 * ph;
            float sn = fmaxf(sqrtf(s2), EPSF);
            float gg = artanh_clip(sn) / sn;

            float cp_ = q1 * fp;            // coeff of raw mx
            float cm  = q2 * a1 * fu;       // coeff of mh
            float cb  = q2 * c1;            // coeff of b

            float v[8]; float s_v2 = 0.0f;
            #pragma unroll
            for (int j = 0; j < 8; j++) {
                float sv = cp_ * p[j] + cm * m[j] + cb * bv[j];
                float vv = tanhf(gg * sv);
                v[j] = vv; s_v2 += vv * vv;
            }
            float vv2[1] = { s_v2 };
            block_reduce4<1>(vv2, redbuf);
            float vn = fmaxf(sqrtf(vv2[0]), EPSF);
            float kk = tanhf(vn) / vn;

            __nv_bfloat16* hrow = hs + (size_t)b * KP2;
            float* orow = out + (size_t)b * HH;
            #pragma unroll
            for (int j = 0; j < 8; j++) {
                int e = tid + j * 128;
                float hv = kk * v[j];
                __nv_bfloat16 hi = __float2bfloat16(hv);
                __nv_bfloat16 lo = __float2bfloat16(hv - __bfloat162float(hi));
                hrow[e] = hi;
                hrow[EE + e] = lo;
                if (t == TT - 1) orow[e] = hv;
            }
            hn_loc[r] = fmaxf(tanhf(vn), EPSF);
        }
        grid_barrier();
    }
}

// ---------------- launch ----------------
extern "C" void kernel_launch(void* const* d_in, const int* in_sizes, int n_in,
                              void* d_out, int out_size)
{
    const float* inp  = (const float*)d_in[0];   // [B,T,E]
    const float* W_ih = (const float*)d_in[1];   // [E,H]
    const float* W_hh = (const float*)d_in[2];   // [H,H]
    const float* b_h  = (const float*)d_in[3];   // [H]
    float* out = (float*)d_out;                  // [B,H]

    __nv_bfloat16 *Xs, *WihT, *WhhT, *hs;
    float *prem, *mh, *xn;
    cudaGetSymbolAddress((void**)&Xs,   g_Xs);
    cudaGetSymbolAddress((void**)&WihT, g_WihT);
    cudaGetSymbolAddress((void**)&WhhT, g_WhhT);
    cudaGetSymbolAddress((void**)&hs,   g_hs);
    cudaGetSymbolAddress((void**)&prem, g_prem);
    cudaGetSymbolAddress((void**)&mh,   g_mh);
    cudaGetSymbolAddress((void**)&xn,   g_xn);

    const int SMEM_BIG = (128 + 128) * 128 * 2;            // 64 KB
    const int SMEM_REC = 12 * 128 * 128 + 2 * 64 * 128;    // 192KB + 16KB = 208 KB
    cudaFuncSetAttribute(big_gemm_kernel,
                         cudaFuncAttributeMaxDynamicSharedMemorySize, SMEM_BIG);
    cudaFuncSetAttribute(recurrence_kernel,
                         cudaFuncAttributeMaxDynamicSharedMemorySize, SMEM_REC);

    // init split hidden = 0
    {
        int n = (int)((size_t)BB * KP2 / 2);
        init_kernel<<<(n + 255) / 256, 256>>>((uint32_t*)hs);
    }

    // prep: split/transpose weights; split X + row norms
    {
        dim3 gw(HH / 32, HH / 32);
        splitWT_kernel<<<gw, 256>>>(W_ih, WihT);
        splitWT_kernel<<<gw, 256>>>(W_hh, WhhT);
        splitX_kernel<<<BB * TT, 256>>>(inp, Xs, xn);
    }

    // big GEMM: raw prem = Xs @ WihT^T  [32768, 1024]
    {
        dim3 grid(HH / 128, (BB * TT) / 128);
        big_gemm_kernel<<<grid, 256, SMEM_BIG>>>(Xs, WihT, prem);
    }

    // persistent recurrence: one kernel for all 128 steps
    recurrence_kernel<<<PK_NCTA, 128, SMEM_REC>>>(WhhT, prem, b_h, xn, hs, mh, out);
}

// round 6
// speedup vs baseline: 1.0896x; 1.0896x over previous
#include <cuda_runtime.h>
#include <cuda_bf16.h>
#include <cuda_fp16.h>
#include <math.h>
#include <stdint.h>

// ---------------- problem constants ----------------
#define BB   256      // batch
#define TT   128      // time steps
#define EE   1024     // input dim
#define HH   1024     // hidden dim
#define KP   3072     // recurrence logical K' = 3*1024 (hi*hi + hi*lo + lo*hi)
#define KP2  2048     // physical 2-segment layout [hi|lo]
#define HKP  2048     // big-GEMM fp16 K' = 2*1024
#define EPSF 1e-6f
#define XSC  32.0f    // pre-scale per side for fp16 split (result /1024)

// ---------------- scratch ----------------
__device__ __half        g_Xs  [(size_t)BB * TT * HKP]; // X fp16 split [B*T, 2E] (hi|lo), x*32
__device__ __half        g_WihT[(size_t)HH * HKP];      // W_ih^T fp16 [H, 2E] (hi|hi), W*32
__device__ __nv_bfloat16 g_WhhT[(size_t)HH * KP];       // W_hh^T bf16 [H, 3H] (hi|lo|hi)
__device__ __nv_bfloat16 g_hs  [(size_t)BB * KP2];      // h split [B, 2H] (hi|lo)
__device__ float g_prem[(size_t)BB * TT * HH];          // RAW X@W_ih, all t
__device__ float g_mh  [4 * (size_t)BB * HH];           // 4 split-K partials of h @ W_hh
__device__ float g_xn  [(size_t)BB * TT];               // ||x_t|| per row (clamped)
__device__ unsigned g_bar_cnt = 0;
__device__ unsigned g_bar_gen = 0;

// logical chunk cg (0..47) -> physical A k-offset in [hi|lo] layout (hi,hi,lo)
__device__ __forceinline__ int a_koff_seg(int cg) {
    return (((cg >> 4) == 2) ? 1024 : 0) + ((cg & 15) << 6);
}

// ---------------- PTX helpers (sm_80-level) ----------------
__device__ __forceinline__ uint32_t smem_u32(const void* p) {
    uint32_t a;
    asm("{ .reg .u64 t; cvta.to.shared.u64 t, %1; cvt.u32.u64 %0, t; }" : "=r"(a) : "l"(p));
    return a;
}
__device__ __forceinline__ void cpasync16(uint32_t s, const void* g) {
    asm volatile("cp.async.cg.shared.global [%0], [%1], 16;" :: "r"(s), "l"(g));
}
#define CP_COMMIT() asm volatile("cp.async.commit_group;" ::: "memory")
#define CP_WAIT1()  asm volatile("cp.async.wait_group 1;" ::: "memory")
#define CP_WAIT2()  asm volatile("cp.async.wait_group 2;" ::: "memory")

__device__ __forceinline__ void ldsm_x4(uint32_t& r0, uint32_t& r1, uint32_t& r2, uint32_t& r3,
                                        uint32_t addr) {
    asm volatile("ldmatrix.sync.aligned.m8n8.x4.shared.b16 {%0,%1,%2,%3}, [%4];"
                 : "=r"(r0), "=r"(r1), "=r"(r2), "=r"(r3) : "r"(addr));
}
__device__ __forceinline__ void mma_bf16(float& d0, float& d1, float& d2, float& d3,
                                         uint32_t a0, uint32_t a1, uint32_t a2, uint32_t a3,
                                         uint32_t b0, uint32_t b1) {
    asm volatile(
        "mma.sync.aligned.m16n8k16.row.col.f32.bf16.bf16.f32 "
        "{%0,%1,%2,%3}, {%4,%5,%6,%7}, {%8,%9}, {%0,%1,%2,%3};"
        : "+f"(d0), "+f"(d1), "+f"(d2), "+f"(d3)
        : "r"(a0), "r"(a1), "r"(a2), "r"(a3), "r"(b0), "r"(b1));
}
__device__ __forceinline__ void mma_fp16(float& d0, float& d1, float& d2, float& d3,
                                         uint32_t a0, uint32_t a1, uint32_t a2, uint32_t a3,
                                         uint32_t b0, uint32_t b1) {
    asm volatile(
        "mma.sync.aligned.m16n8k16.row.col.f32.f16.f16.f32 "
        "{%0,%1,%2,%3}, {%4,%5,%6,%7}, {%8,%9}, {%0,%1,%2,%3};"
        : "+f"(d0), "+f"(d1), "+f"(d2), "+f"(d3)
        : "r"(a0), "r"(a1), "r"(a2), "r"(a3), "r"(b0), "r"(b1));
}

// ---------------- init ----------------
__global__ void init_kernel(uint32_t* hs_u32) {
    int i = blockIdx.x * blockDim.x + threadIdx.x;
    if (i < (int)((size_t)BB * KP2 / 2)) hs_u32[i] = 0u;
}

// ---------------- splitX: fp16 hi/lo of 32*x, plus ||x|| ----------------
__global__ __launch_bounds__(256) void splitX_kernel(const float* __restrict__ X,
                                                     __half* __restrict__ Xs,
                                                     float* __restrict__ xn) {
    __shared__ float sh[8];
    size_t r = blockIdx.x;
    const float* x = X + r * EE;
    __half* row = Xs + r * HKP;
    float x2 = 0.0f;
    #pragma unroll
    for (int j = 0; j < 4; j++) {
        int e = threadIdx.x + j * 256;
        float v = x[e];
        x2 += v * v;
        float vs = v * XSC;
        __half hi = __float2half_rn(vs);
        __half lo = __float2half_rn(vs - __half2float(hi));
        row[e] = hi;
        row[EE + e] = lo;
    }
    #pragma unroll
    for (int o = 16; o > 0; o >>= 1) x2 += __shfl_down_sync(0xffffffffu, x2, o);
    if ((threadIdx.x & 31) == 0) sh[threadIdx.x >> 5] = x2;
    __syncthreads();
    if (threadIdx.x == 0) {
        float s = 0.0f;
        #pragma unroll
        for (int w = 0; w < 8; w++) s += sh[w];
        xn[r] = fmaxf(sqrtf(s), EPSF);
    }
}

// ---------------- W_ih [K,N] -> fp16 Wt [N, 2K] (hi|hi), scaled, transposed ----
__global__ __launch_bounds__(256) void splitWih_kernel(const float* __restrict__ W,
                                                       __half* __restrict__ Wt) {
    __shared__ float tile[32][33];
    int n0 = blockIdx.x * 32;
    int k0 = blockIdx.y * 32;
    int tx = threadIdx.x & 31;
    int ty = threadIdx.x >> 5;
    #pragma unroll
    for (int i = 0; i < 32; i += 8)
        tile[ty + i][tx] = W[(size_t)(k0 + ty + i) * HH + n0 + tx];
    __syncthreads();
    #pragma unroll
    for (int i = 0; i < 32; i += 8) {
        float v = tile[tx][ty + i] * XSC;
        int n = n0 + ty + i;
        int k = k0 + tx;
        __half hi = __float2half_rn(v);
        __half* row = Wt + (size_t)n * HKP;
        row[k] = hi;            // seg 0: Bh (pairs with Ah)
        row[EE + k] = hi;       // seg 1: Bh (pairs with Al)
    }
}

// ---------------- W_hh [K,N] -> bf16 Wt [N, 3K] (hi|lo|hi), transposed ----
__global__ __launch_bounds__(256) void splitWhh_kernel(const float* __restrict__ W,
                                                       __nv_bfloat16* __restrict__ Wt) {
    __shared__ float tile[32][33];
    int n0 = blockIdx.x * 32;
    int k0 = blockIdx.y * 32;
    int tx = threadIdx.x & 31;
    int ty = threadIdx.x >> 5;
    #pragma unroll
    for (int i = 0; i < 32; i += 8)
        tile[ty + i][tx] = W[(size_t)(k0 + ty + i) * HH + n0 + tx];
    __syncthreads();
    #pragma unroll
    for (int i = 0; i < 32; i += 8) {
        float v = tile[tx][ty + i];
        int n = n0 + ty + i;
        int k = k0 + tx;
        __nv_bfloat16 hi = __float2bfloat16(v);
        __nv_bfloat16 lo = __float2bfloat16(v - __bfloat162float(hi));
        __nv_bfloat16* row = Wt + (size_t)n * KP;
        row[k] = hi;
        row[HH + k] = lo;
        row[2 * HH + k] = hi;
    }
}

// ---------------- big GEMM (fp16, 2-seg): prem_raw = Xs @ WihT^T / 1024 --------
// BM=BN=128, 256 thr (2x4 warps), 3-stage cp.async, 32 chunks of 64.
__global__ void __launch_bounds__(256, 2)
big_gemm_kernel(const __half* __restrict__ A,
                const __half* __restrict__ B,
                float* __restrict__ C)
{
    constexpr int ABYTES = 128 * 128, BBYTES = 128 * 128;
    constexpr int NCH = HKP / 64;     // 32
    extern __shared__ char smem[];
    uint32_t sbase = smem_u32(smem);
    uint32_t sA[3], sB[3];
    #pragma unroll
    for (int s = 0; s < 3; s++) {
        sA[s] = sbase + s * (ABYTES + BBYTES);
        sB[s] = sA[s] + ABYTES;
    }

    int tid  = threadIdx.x;
    int warp = tid >> 5;
    int lane = tid & 31;
    int wm = warp & 1;         // WARP_M = 64, MT = 4
    int wn = warp >> 1;        // WARP_N = 32, NT8 = 4

    size_t rowTile = (size_t)blockIdx.y * 128;
    size_t colTile = (size_t)blockIdx.x * 128;
    const __half* Abase = A + rowTile * HKP;
    const __half* Bbase = B + colTile * HKP;

    float acc[4][4][4];
    #pragma unroll
    for (int i = 0; i < 4; i++)
        #pragma unroll
        for (int j = 0; j < 4; j++)
            #pragma unroll
            for (int e = 0; e < 4; e++) acc[i][j][e] = 0.0f;

    auto load_stage = [&](int st, int c) {
        const __half* Ag = Abase + (size_t)c * 64;
        const __half* Bg = Bbase + (size_t)c * 64;
        #pragma unroll
        for (int u = tid; u < 128 * 8; u += 256) {
            int row = u >> 3, ch = u & 7;
            uint32_t phys = (uint32_t)(row * 128 + ((ch ^ (row & 7)) << 4));
            cpasync16(sA[st] + phys, Ag + (size_t)row * HKP + ch * 8);
        }
        #pragma unroll
        for (int u = tid; u < 128 * 8; u += 256) {
            int row = u >> 3, ch = u & 7;
            uint32_t phys = (uint32_t)(row * 128 + ((ch ^ (row & 7)) << 4));
            cpasync16(sB[st] + phys, Bg + (size_t)row * HKP + ch * 8);
        }
    };

    load_stage(0, 0); CP_COMMIT();
    load_stage(1, 1); CP_COMMIT();

    int st = 0;
    for (int c = 0; c < NCH; c++) {
        if (c + 2 < NCH) load_stage((st + 2) % 3, c + 2);
        CP_COMMIT();
        CP_WAIT2();
        __syncthreads();

        uint32_t a = sA[st], b = sB[st];
        #pragma unroll
        for (int s = 0; s < 4; s++) {
            uint32_t af[4][4];
            #pragma unroll
            for (int i = 0; i < 4; i++) {
                int row = wm * 64 + i * 16 + (lane & 15);
                int ch  = 2 * s + (lane >> 4);
                ldsm_x4(af[i][0], af[i][1], af[i][2], af[i][3],
                        a + row * 128 + ((ch ^ (row & 7)) << 4));
            }
            uint32_t bfm[2][4];
            #pragma unroll
            for (int j = 0; j < 2; j++) {
                int row = wn * 32 + j * 16 + (lane & 7) + ((lane >> 4) << 3);
                int ch  = 2 * s + ((lane >> 3) & 1);
                ldsm_x4(bfm[j][0], bfm[j][1], bfm[j][2], bfm[j][3],
                        b + row * 128 + ((ch ^ (row & 7)) << 4));
            }
            #pragma unroll
            for (int i = 0; i < 4; i++)
                #pragma unroll
                for (int nj = 0; nj < 4; nj++)
                    mma_fp16(acc[i][nj][0], acc[i][nj][1], acc[i][nj][2], acc[i][nj][3],
                             af[i][0], af[i][1], af[i][2], af[i][3],
                             bfm[nj >> 1][(nj & 1) * 2], bfm[nj >> 1][(nj & 1) * 2 + 1]);
        }
        __syncthreads();
        st = (st + 1) % 3;
    }

    const float SC = 1.0f / (XSC * XSC);
    int g = lane >> 2, t4 = lane & 3;
    #pragma unroll
    for (int i = 0; i < 4; i++)
        #pragma unroll
        for (int nj = 0; nj < 4; nj++) {
            size_t row0 = rowTile + wm * 64 + i * 16 + g;
            size_t col  = colTile + wn * 32 + nj * 8 + 2 * t4;
            *reinterpret_cast<float2*>(&C[row0 * HH + col]) =
                make_float2(acc[i][nj][0] * SC, acc[i][nj][1] * SC);
            *reinterpret_cast<float2*>(&C[(row0 + 8) * HH + col]) =
                make_float2(acc[i][nj][2] * SC, acc[i][nj][3] * SC);
        }
}

// ---------------- helpers for step math ----------------
template <int NV>
__device__ __forceinline__ void block_reduce8(float* vals, float* shbuf /* NV*8 */) {
    __syncthreads();
    #pragma unroll
    for (int v = 0; v < NV; v++) {
        float x = vals[v];
        #pragma unroll
        for (int o = 16; o > 0; o >>= 1) x += __shfl_down_sync(0xffffffffu, x, o);
        if ((threadIdx.x & 31) == 0) shbuf[v * 8 + (threadIdx.x >> 5)] = x;
    }
    __syncthreads();
    #pragma unroll
    for (int v = 0; v < NV; v++) {
        float s = 0.0f;
        #pragma unroll
        for (int w = 0; w < 8; w++) s += shbuf[v * 8 + w];
        vals[v] = s;
    }
}
__device__ __forceinline__ float artanh_clip(float x) {
    return atanhf(fminf(x, 1.0f - 1e-6f));
}

// ---------------- persistent recurrence kernel (256 thr, 128 CTAs) ----------
#define PK_NCTA 128

__device__ __forceinline__ void grid_barrier() {
    __threadfence();
    __syncthreads();
    if (threadIdx.x == 0) {
        unsigned gen = *(volatile unsigned*)&g_bar_gen;
        unsigned old = atomicAdd(&g_bar_cnt, 1u);
        if (old == PK_NCTA - 1) {
            g_bar_cnt = 0;
            __threadfence();
            atomicExch(&g_bar_gen, gen + 1);
        } else {
            while (*(volatile unsigned*)&g_bar_gen == gen) { __nanosleep(32); }
        }
        __threadfence();
    }
    __syncthreads();
}

__global__ void __launch_bounds__(256, 1)
recurrence_kernel(const __nv_bfloat16* __restrict__ W,  // WhhT [H, 3H]
                  const float* __restrict__ prem,       // raw [B,T,H]
                  const float* __restrict__ bvec,       // b_h
                  const float* __restrict__ xn_arr,     // [B*T]
                  __nv_bfloat16* __restrict__ hs,       // [B, 2H]
                  float* __restrict__ mh,               // [4][B][H]
                  float* __restrict__ out)              // [B,H]
{
    constexpr int BCH = 12;                 // 12 chunks of 64 = 768 K-quarter
    constexpr int CHB = 128 * 128;          // bytes per resident-B chunk
    extern __shared__ char smem[];
    __shared__ float redbuf[6 * 8];
    uint32_t sbase = smem_u32(smem);
    uint32_t sBres = sbase;                 // 192 KB resident B
    uint32_t sA[2] = { sbase + BCH * CHB, sbase + BCH * CHB + 64 * 128 };

    int bid  = blockIdx.x;
    int z = bid & 3;                        // K quarter
    int x = (bid >> 2) & 7;                 // col tile (128 wide)
    int y = bid >> 5;                       // row tile (64 tall)
    int tid  = threadIdx.x;
    int warp = tid >> 5;
    int lane = tid & 31;
    int wm = warp & 1;                      // WARP_M = 32, MT = 2
    int wn = warp >> 1;                     // WARP_N = 32, NT8 = 4

    // resident B: rows [x*128, +128) of W, K [z*768, +768)
    {
        const __nv_bfloat16* Wb = W + (size_t)(x * 128) * KP + (size_t)z * 768;
        for (int u = tid; u < BCH * 128 * 8; u += 256) {
            int c   = u / (128 * 8);
            int rem = u - c * (128 * 8);
            int row = rem >> 3, ch = rem & 7;
            uint32_t phys = (uint32_t)(c * CHB + row * 128 + ((ch ^ (row & 7)) << 4));
            cpasync16(sBres + phys, Wb + (size_t)row * KP + c * 64 + ch * 8);
        }
        CP_COMMIT();
    }

    const __nv_bfloat16* Abase = hs + (size_t)(y * 64) * KP2;
    float* mhz = mh + (size_t)z * BB * HH;

    float hn_loc[2] = { EPSF, EPSF };
    int b0 = bid * 2;

    auto loadA = [&](int st, int c) {       // A chunk: 64 rows x 64 k
        int koff = a_koff_seg(z * BCH + c);
        #pragma unroll
        for (int u = tid; u < 64 * 8; u += 256) {
            int row = u >> 3, ch = u & 7;
            uint32_t phys = (uint32_t)(row * 128 + ((ch ^ (row & 7)) << 4));
            cpasync16(sA[st] + phys, Abase + (size_t)row * KP2 + koff + ch * 8);
        }
    };

    for (int t = 0; t < TT; t++) {
        // ===== GEMM phase: mh[z] tile = hs_tile @ Wres^T =====
        float acc[2][4][4];
        #pragma unroll
        for (int i = 0; i < 2; i++)
            #pragma unroll
            for (int j = 0; j < 4; j++)
                #pragma unroll
                for (int e = 0; e < 4; e++) acc[i][j][e] = 0.0f;

        loadA(0, 0);
        CP_COMMIT();
        for (int c = 0; c < BCH; c++) {
            if (c + 1 < BCH) loadA((c + 1) & 1, c + 1);
            CP_COMMIT();
            CP_WAIT1();
            __syncthreads();

            uint32_t a = sA[c & 1];
            uint32_t b = sBres + c * CHB;
            #pragma unroll
            for (int s = 0; s < 4; s++) {
                uint32_t af[2][4];
                #pragma unroll
                for (int i = 0; i < 2; i++) {
                    int row = wm * 32 + i * 16 + (lane & 15);
                    int ch  = 2 * s + (lane >> 4);
                    ldsm_x4(af[i][0], af[i][1], af[i][2], af[i][3],
                            a + row * 128 + ((ch ^ (row & 7)) << 4));
                }
                uint32_t bfm[2][4];
                #pragma unroll
                for (int j = 0; j < 2; j++) {
                    int row = wn * 32 + j * 16 + (lane & 7) + ((lane >> 4) << 3);
                    int ch  = 2 * s + ((lane >> 3) & 1);
                    ldsm_x4(bfm[j][0], bfm[j][1], bfm[j][2], bfm[j][3],
                            b + row * 128 + ((ch ^ (row & 7)) << 4));
                }
                #pragma unroll
                for (int i = 0; i < 2; i++)
                    #pragma unroll
                    for (int nj = 0; nj < 4; nj++)
                        mma_bf16(acc[i][nj][0], acc[i][nj][1], acc[i][nj][2], acc[i][nj][3],
                                 af[i][0], af[i][1], af[i][2], af[i][3],
                                 bfm[nj >> 1][(nj & 1) * 2], bfm[nj >> 1][(nj & 1) * 2 + 1]);
            }
            __syncthreads();
        }

        // epilogue -> mh[z]
        {
            int g = lane >> 2, t4 = lane & 3;
            #pragma unroll
            for (int i = 0; i < 2; i++)
                #pragma unroll
                for (int nj = 0; nj < 4; nj++) {
                    size_t row0 = (size_t)(y * 64 + wm * 32 + i * 16 + g);
                    size_t col  = (size_t)(x * 128 + wn * 32 + nj * 8 + 2 * t4);
                    *reinterpret_cast<float2*>(&mhz[row0 * HH + col]) =
                        make_float2(acc[i][nj][0], acc[i][nj][1]);
                    *reinterpret_cast<float2*>(&mhz[(row0 + 8) * HH + col]) =
                        make_float2(acc[i][nj][2], acc[i][nj][3]);
                }
        }
        grid_barrier();

        // ===== STEP phase: rows b0, b0+1 =====
        for (int r = 0; r < 2; r++) {
            int b = b0 + r;
            const float* pr = prem + ((size_t)b * TT + t) * HH;
            float p[4], m[4], bv[4];
            float s_mx2 = 0, s_mxm = 0, s_mxb = 0, s_m2 = 0, s_mb = 0, s_b2 = 0;
            #pragma unroll
            for (int j = 0; j < 4; j++) {
                int e = tid + j * 256;
                float mv = __ldcv(&mh[(size_t)0 * BB * HH + (size_t)b * HH + e])
                         + __ldcv(&mh[(size_t)1 * BB * HH + (size_t)b * HH + e])
                         + __ldcv(&mh[(size_t)2 * BB * HH + (size_t)b * HH + e])
                         + __ldcv(&mh[(size_t)3 * BB * HH + (size_t)b * HH + e]);
                float pv = pr[e];
                float bb = bvec[e];
                m[j] = mv; p[j] = pv; bv[j] = bb;
                s_mx2 += pv * pv;  s_mxm += pv * mv;  s_mxb += pv * bb;
                s_m2  += mv * mv;  s_mb  += mv * bb;  s_b2  += bb * bb;
            }
            float vals[6] = { s_mx2, s_mxm, s_mxb, s_m2, s_mb, s_b2 };
            block_reduce8<6>(vals, redbuf);
            float mx2 = vals[0], mxm = vals[1], mxb = vals[2];
            float m2  = vals[3], mb  = vals[4], b2  = vals[5];

            float xn  = xn_arr[(size_t)b * TT + t];
            float mxn = fmaxf(sqrtf(mx2), EPSF);
            float fp  = tanhf(mxn / xn * artanh_clip(xn)) / mxn;
            float p2  = fp * fp * mx2;
            float pm  = fp * mxm;
            float pb  = fp * mxb;

            float hn  = hn_loc[r];
            float mhn = fmaxf(sqrtf(m2), EPSF);
            float fu  = tanhf(mhn / hn * artanh_clip(hn)) / mhn;
            float u2  = fu * fu * m2;
            float ub  = fu * mb;

            float den1 = fmaxf(1.0f + 2.0f * ub + u2 * b2, EPSF);
            float a1 = (1.0f + 2.0f * ub + b2) / den1;
            float c1 = (1.0f - u2) / den1;
            float hid2 = a1 * a1 * u2 + 2.0f * a1 * c1 * ub + c1 * c1 * b2;
            float ph   = a1 * fu * pm + c1 * pb;

            float den2 = fmaxf(1.0f + 2.0f * ph + p2 * hid2, EPSF);
            float q1 = (1.0f + 2.0f * ph + hid2) / den2;
            float q2 = (1.0f - p2) / den2;
            float s2 = q1 * q1 * p2 + q2 * q2 * hid2 + 2.0f * q1 * q2 * ph;
            float sn = fmaxf(sqrtf(s2), EPSF);
            float gg = artanh_clip(sn) / sn;

            float cp_ = q1 * fp;
            float cm  = q2 * a1 * fu;
            float cb  = q2 * c1;

            float v[4]; float s_v2 = 0.0f;
            #pragma unroll
            for (int j = 0; j < 4; j++) {
                float sv = cp_ * p[j] + cm * m[j] + cb * bv[j];
                float vv = tanhf(gg * sv);
                v[j] = vv; s_v2 += vv * vv;
            }
            float vv2[1] = { s_v2 };
            block_reduce8<1>(vv2, redbuf);
            float vn = fmaxf(sqrtf(vv2[0]), EPSF);
            float kk = tanhf(vn) / vn;

            __nv_bfloat16* hrow = hs + (size_t)b * KP2;
            float* orow = out + (size_t)b * HH;
            #pragma unroll
            for (int j = 0; j < 4; j++) {
                int e = tid + j * 256;
                float hv = kk * v[j];
                __nv_bfloat16 hi = __float2bfloat16(hv);
                __nv_bfloat16 lo = __float2bfloat16(hv - __bfloat162float(hi));
                hrow[e] = hi;
                hrow[EE + e] = lo;
                if (t == TT - 1) orow[e] = hv;
            }
            hn_loc[r] = fmaxf(tanhf(vn), EPSF);
        }
        grid_barrier();
    }
}

// ---------------- launch ----------------
extern "C" void kernel_launch(void* const* d_in, const int* in_sizes, int n_in,
                              void* d_out, int out_size)
{
    const float* inp  = (const float*)d_in[0];   // [B,T,E]
    const float* W_ih = (const float*)d_in[1];   // [E,H]
    const float* W_hh = (const float*)d_in[2];   // [H,H]
    const float* b_h  = (const float*)d_in[3];   // [H]
    float* out = (float*)d_out;                  // [B,H]

    __half *Xs, *WihT;
    __nv_bfloat16 *WhhT, *hs;
    float *prem, *mh, *xn;
    cudaGetSymbolAddress((void**)&Xs,   g_Xs);
    cudaGetSymbolAddress((void**)&WihT, g_WihT);
    cudaGetSymbolAddress((void**)&WhhT, g_WhhT);
    cudaGetSymbolAddress((void**)&hs,   g_hs);
    cudaGetSymbolAddress((void**)&prem, g_prem);
    cudaGetSymbolAddress((void**)&mh,   g_mh);
    cudaGetSymbolAddress((void**)&xn,   g_xn);

    const int SMEM_BIG = 3 * (128 + 128) * 128;            // 96 KB (3 stages)
    const int SMEM_REC = 12 * 128 * 128 + 2 * 64 * 128;    // 208 KB
    cudaFuncSetAttribute(big_gemm_kernel,
                         cudaFuncAttributeMaxDynamicSharedMemorySize, SMEM_BIG);
    cudaFuncSetAttribute(recurrence_kernel,
                         cudaFuncAttributeMaxDynamicSharedMemorySize, SMEM_REC);

    // init split hidden = 0
    {
        int n = (int)((size_t)BB * KP2 / 2);
        init_kernel<<<(n + 255) / 256, 256>>>((uint32_t*)hs);
    }

    // prep: weight splits + X split/norms
    {
        dim3 gw(HH / 32, HH / 32);
        splitWih_kernel<<<gw, 256>>>(W_ih, WihT);
        splitWhh_kernel<<<gw, 256>>>(W_hh, WhhT);
        splitX_kernel<<<BB * TT, 256>>>(inp, Xs, xn);
    }

    // big GEMM: raw prem = Xs @ WihT^T  [32768, 1024] (fp16 2-seg)
    {
        dim3 grid(HH / 128, (BB * TT) / 128);
        big_gemm_kernel<<<grid, 256, SMEM_BIG>>>(Xs, WihT, prem);
    }

    // persistent recurrence: one kernel for all 128 steps
    recurrence_kernel<<<PK_NCTA, 256, SMEM_REC>>>(WhhT, prem, b_h, xn, hs, mh, out);
}

// round 9
// speedup vs baseline: 1.2159x; 1.1159x over previous
#include <cuda_runtime.h>
#include <cuda_bf16.h>
#include <cuda_fp16.h>
#include <math.h>
#include <stdint.h>

// ---------------- problem constants ----------------
#define BB   256      // batch
#define TT   128      // time steps
#define EE   1024     // input dim
#define HH   1024     // hidden dim
#define KP2  2048     // fp16 2-segment K' (both GEMMs)
#define EPSF 1e-6f
#define XSC  32.0f    // pre-scale per side for fp16 split (result /1024)
#define ISC2 (1.0f / (XSC * XSC))

// ---------------- scratch ----------------
__device__ __half g_Xs   [(size_t)BB * TT * KP2]; // X fp16 split [B*T, 2E] (hi|lo), x*32
__device__ __half g_WihT [(size_t)HH * KP2];      // W_ih^T fp16 [H, 2E] (hi|hi), W*32
__device__ __half g_WhhT [(size_t)HH * KP2];      // W_hh^T fp16 [H, 2H] (hi|hi), W*32
__device__ __half g_hs   [(size_t)BB * KP2];      // h fp16 split [B, 2H] (hi|lo), h*32
__device__ float g_prem[(size_t)BB * TT * HH];    // RAW X@W_ih (true scale), all t
__device__ float g_mh  [4 * (size_t)BB * HH];     // 4 split-K partials (scaled x1024)
__device__ float g_xn  [(size_t)BB * TT];         // ||x_t|| per row (clamped)
__device__ unsigned g_bar_cnt = 0;
__device__ unsigned g_bar_gen = 0;

// ---------------- PTX helpers (sm_80-level) ----------------
__device__ __forceinline__ uint32_t smem_u32(const void* p) {
    uint32_t a;
    asm("{ .reg .u64 t; cvta.to.shared.u64 t, %1; cvt.u32.u64 %0, t; }" : "=r"(a) : "l"(p));
    return a;
}
__device__ __forceinline__ void cpasync16(uint32_t s, const void* g) {
    asm volatile("cp.async.cg.shared.global [%0], [%1], 16;" :: "r"(s), "l"(g));
}
#define CP_COMMIT() asm volatile("cp.async.commit_group;" ::: "memory")
#define CP_WAIT1()  asm volatile("cp.async.wait_group 1;" ::: "memory")
#define CP_WAIT2()  asm volatile("cp.async.wait_group 2;" ::: "memory")

__device__ __forceinline__ void ldsm_x4(uint32_t& r0, uint32_t& r1, uint32_t& r2, uint32_t& r3,
                                        uint32_t addr) {
    asm volatile("ldmatrix.sync.aligned.m8n8.x4.shared.b16 {%0,%1,%2,%3}, [%4];"
                 : "=r"(r0), "=r"(r1), "=r"(r2), "=r"(r3) : "r"(addr));
}
__device__ __forceinline__ void mma_fp16(float& d0, float& d1, float& d2, float& d3,
                                         uint32_t a0, uint32_t a1, uint32_t a2, uint32_t a3,
                                         uint32_t b0, uint32_t b1) {
    asm volatile(
        "mma.sync.aligned.m16n8k16.row.col.f32.f16.f16.f32 "
        "{%0,%1,%2,%3}, {%4,%5,%6,%7}, {%8,%9}, {%0,%1,%2,%3};"
        : "+f"(d0), "+f"(d1), "+f"(d2), "+f"(d3)
        : "r"(a0), "r"(a1), "r"(a2), "r"(a3), "r"(b0), "r"(b1));
}

// ---------------- init ----------------
__global__ void init_kernel(uint32_t* hs_u32) {
    int i = blockIdx.x * blockDim.x + threadIdx.x;
    if (i < (int)((size_t)BB * KP2 / 2)) hs_u32[i] = 0u;
}

// ---------------- splitX: fp16 hi/lo of 32*x, plus ||x|| ----------------
__global__ __launch_bounds__(256) void splitX_kernel(const float* __restrict__ X,
                                                     __half* __restrict__ Xs,
                                                     float* __restrict__ xn) {
    __shared__ float sh[8];
    size_t r = blockIdx.x;
    const float* x = X + r * EE;
    __half* row = Xs + r * KP2;
    float x2 = 0.0f;
    #pragma unroll
    for (int j = 0; j < 4; j++) {
        int e = threadIdx.x + j * 256;
        float v = x[e];
        x2 += v * v;
        float vs = v * XSC;
        __half hi = __float2half_rn(vs);
        __half lo = __float2half_rn(vs - __half2float(hi));
        row[e] = hi;
        row[EE + e] = lo;
    }
    #pragma unroll
    for (int o = 16; o > 0; o >>= 1) x2 += __shfl_down_sync(0xffffffffu, x2, o);
    if ((threadIdx.x & 31) == 0) sh[threadIdx.x >> 5] = x2;
    __syncthreads();
    if (threadIdx.x == 0) {
        float s = 0.0f;
        #pragma unroll
        for (int w = 0; w < 8; w++) s += sh[w];
        xn[r] = fmaxf(sqrtf(s), EPSF);
    }
}

// ---------------- W [K,N] -> fp16 Wt [N, 2K] (hi|hi), scaled, transposed ----
__global__ __launch_bounds__(256) void splitW_kernel(const float* __restrict__ W,
                                                     __half* __restrict__ Wt) {
    __shared__ float tile[32][33];
    int n0 = blockIdx.x * 32;
    int k0 = blockIdx.y * 32;
    int tx = threadIdx.x & 31;
    int ty = threadIdx.x >> 5;
    #pragma unroll
    for (int i = 0; i < 32; i += 8)
        tile[ty + i][tx] = W[(size_t)(k0 + ty + i) * HH + n0 + tx];
    __syncthreads();
    #pragma unroll
    for (int i = 0; i < 32; i += 8) {
        float v = tile[tx][ty + i] * XSC;
        int n = n0 + ty + i;
        int k = k0 + tx;
        __half hi = __float2half_rn(v);
        __half* row = Wt + (size_t)n * KP2;
        row[k] = hi;            // seg 0 (pairs with A-hi)
        row[EE + k] = hi;       // seg 1 (pairs with A-lo)
    }
}

// ---------------- big GEMM (fp16, 2-seg): prem_raw = Xs @ WihT^T / 1024 --------
// BM=BN=128, 256 thr (2x4 warps), 3-stage cp.async, 32 chunks of 64.
__global__ void __launch_bounds__(256, 2)
big_gemm_kernel(const __half* __restrict__ A,
                const __half* __restrict__ B,
                float* __restrict__ C)
{
    constexpr int ABYTES = 128 * 128, BBYTES = 128 * 128;
    constexpr int NCH = KP2 / 64;     // 32
    extern __shared__ char smem[];
    uint32_t sbase = smem_u32(smem);
    uint32_t sA[3], sB[3];
    #pragma unroll
    for (int s = 0; s < 3; s++) {
        sA[s] = sbase + s * (ABYTES + BBYTES);
        sB[s] = sA[s] + ABYTES;
    }

    int tid  = threadIdx.x;
    int warp = tid >> 5;
    int lane = tid & 31;
    int wm = warp & 1;         // WARP_M = 64, MT = 4
    int wn = warp >> 1;        // WARP_N = 32, NT8 = 4

    size_t rowTile = (size_t)blockIdx.y * 128;
    size_t colTile = (size_t)blockIdx.x * 128;
    const __half* Abase = A + rowTile * KP2;
    const __half* Bbase = B + colTile * KP2;

    float acc[4][4][4];
    #pragma unroll
    for (int i = 0; i < 4; i++)
        #pragma unroll
        for (int j = 0; j < 4; j++)
            #pragma unroll
            for (int e = 0; e < 4; e++) acc[i][j][e] = 0.0f;

    auto load_stage = [&](int st, int c) {
        const __half* Ag = Abase + (size_t)c * 64;
        const __half* Bg = Bbase + (size_t)c * 64;
        #pragma unroll
        for (int u = tid; u < 128 * 8; u += 256) {
            int row = u >> 3, ch = u & 7;
            uint32_t phys = (uint32_t)(row * 128 + ((ch ^ (row & 7)) << 4));
            cpasync16(sA[st] + phys, Ag + (size_t)row * KP2 + ch * 8);
        }
        #pragma unroll
        for (int u = tid; u < 128 * 8; u += 256) {
            int row = u >> 3, ch = u & 7;
            uint32_t phys = (uint32_t)(row * 128 + ((ch ^ (row & 7)) << 4));
            cpasync16(sB[st] + phys, Bg + (size_t)row * KP2 + ch * 8);
        }
    };

    load_stage(0, 0); CP_COMMIT();
    load_stage(1, 1); CP_COMMIT();

    int st = 0;
    for (int c = 0; c < NCH; c++) {
        if (c + 2 < NCH) load_stage((st + 2) % 3, c + 2);
        CP_COMMIT();
        CP_WAIT2();
        __syncthreads();

        uint32_t a = sA[st], b = sB[st];
        #pragma unroll
        for (int s = 0; s < 4; s++) {
            uint32_t af[4][4];
            #pragma unroll
            for (int i = 0; i < 4; i++) {
                int row = wm * 64 + i * 16 + (lane & 15);
                int ch  = 2 * s + (lane >> 4);
                ldsm_x4(af[i][0], af[i][1], af[i][2], af[i][3],
                        a + row * 128 + ((ch ^ (row & 7)) << 4));
            }
            uint32_t bfm[2][4];
            #pragma unroll
            for (int j = 0; j < 2; j++) {
                int row = wn * 32 + j * 16 + (lane & 7) + ((lane >> 4) << 3);
                int ch  = 2 * s + ((lane >> 3) & 1);
                ldsm_x4(bfm[j][0], bfm[j][1], bfm[j][2], bfm[j][3],
                        b + row * 128 + ((ch ^ (row & 7)) << 4));
            }
            #pragma unroll
            for (int i = 0; i < 4; i++)
                #pragma unroll
                for (int nj = 0; nj < 4; nj++)
                    mma_fp16(acc[i][nj][0], acc[i][nj][1], acc[i][nj][2], acc[i][nj][3],
                             af[i][0], af[i][1], af[i][2], af[i][3],
                             bfm[nj >> 1][(nj & 1) * 2], bfm[nj >> 1][(nj & 1) * 2 + 1]);
        }
        __syncthreads();
        st = (st + 1) % 3;
    }

    int g = lane >> 2, t4 = lane & 3;
    #pragma unroll
    for (int i = 0; i < 4; i++)
        #pragma unroll
        for (int nj = 0; nj < 4; nj++) {
            size_t row0 = rowTile + wm * 64 + i * 16 + g;
            size_t col  = colTile + wn * 32 + nj * 8 + 2 * t4;
            *reinterpret_cast<float2*>(&C[row0 * HH + col]) =
                make_float2(acc[i][nj][0] * ISC2, acc[i][nj][1] * ISC2);
            *reinterpret_cast<float2*>(&C[(row0 + 8) * HH + col]) =
                make_float2(acc[i][nj][2] * ISC2, acc[i][nj][3] * ISC2);
        }
}

// ---------------- helpers for step math ----------------
template <int NV>
__device__ __forceinline__ void block_reduce8(float* vals, float* shbuf /* NV*8 */) {
    __syncthreads();
    #pragma unroll
    for (int v = 0; v < NV; v++) {
        float x = vals[v];
        #pragma unroll
        for (int o = 16; o > 0; o >>= 1) x += __shfl_down_sync(0xffffffffu, x, o);
        if ((threadIdx.x & 31) == 0) shbuf[v * 8 + (threadIdx.x >> 5)] = x;
    }
    __syncthreads();
    #pragma unroll
    for (int v = 0; v < NV; v++) {
        float s = 0.0f;
        #pragma unroll
        for (int w = 0; w < 8; w++) s += shbuf[v * 8 + w];
        vals[v] = s;
    }
}
__device__ __forceinline__ float artanh_clip(float x) {
    return atanhf(fminf(x, 1.0f - 1e-6f));
}

// ---------------- persistent recurrence kernel (256 thr, 128 CTAs) ----------
#define PK_NCTA 128

__device__ __forceinline__ void grid_barrier() {
    __threadfence();
    __syncthreads();
    if (threadIdx.x == 0) {
        unsigned gen = *(volatile unsigned*)&g_bar_gen;
        unsigned old = atomicAdd(&g_bar_cnt, 1u);
        if (old == PK_NCTA - 1) {
            g_bar_cnt = 0;
            __threadfence();
            atomicExch(&g_bar_gen, gen + 1);
        } else {
            while (*(volatile unsigned*)&g_bar_gen == gen) { __nanosleep(16); }
        }
        __threadfence();
    }
    __syncthreads();
}

__global__ void __launch_bounds__(256, 1)
recurrence_kernel(const __half* __restrict__ W,        // WhhT [H, 2H] fp16 (hi|hi)
                  const float* __restrict__ prem,      // raw [B,T,H]
                  const float* __restrict__ bvec,      // b_h
                  const float* __restrict__ xn_arr,    // [B*T]
                  __half* __restrict__ hs,             // [B, 2H] fp16 (hi|lo)
                  float* __restrict__ mh,              // [4][B][H] (x1024 scaled)
                  float* __restrict__ out)             // [B,H]
{
    constexpr int BCH = 8;                  // 8 chunks of 64 = 512 K-quarter
    constexpr int CHB = 128 * 128;          // bytes per resident-B chunk
    extern __shared__ char smem[];
    __shared__ float redbuf[6 * 8];
    uint32_t sbase = smem_u32(smem);
    uint32_t sBres = sbase;                 // 128 KB resident B
    uint32_t sA[2] = { sbase + BCH * CHB, sbase + BCH * CHB + 64 * 128 };

    int bid  = blockIdx.x;
    int z = bid & 3;                        // K quarter (512 wide)
    int x = (bid >> 2) & 7;                 // col tile (128 wide)
    int y = bid >> 5;                       // row tile (64 tall)
    int tid  = threadIdx.x;
    int warp = tid >> 5;
    int lane = tid & 31;
    int wm = warp & 1;                      // WARP_M = 32, MT = 2
    int wn = warp >> 1;                     // WARP_N = 32, NT8 = 4

    // resident B: rows [x*128, +128) of W, K [z*512, +512)
    {
        const __half* Wb = W + (size_t)(x * 128) * KP2 + (size_t)z * 512;
        for (int u = tid; u < BCH * 128 * 8; u += 256) {
            int c   = u / (128 * 8);
            int rem = u - c * (128 * 8);
            int row = rem >> 3, ch = rem & 7;
            uint32_t phys = (uint32_t)(c * CHB + row * 128 + ((ch ^ (row & 7)) << 4));
            cpasync16(sBres + phys, Wb + (size_t)row * KP2 + c * 64 + ch * 8);
        }
        CP_COMMIT();
    }

    const __half* Abase = hs + (size_t)(y * 64) * KP2;
    float* mhz = mh + (size_t)z * BB * HH;
    int koff0 = z * 512;

    float hn_loc[2] = { EPSF, EPSF };
    int b0 = bid * 2;

    auto loadA = [&](int st, int c) {       // A chunk: 64 rows x 64 k
        #pragma unroll
        for (int u = tid; u < 64 * 8; u += 256) {
            int row = u >> 3, ch = u & 7;
            uint32_t phys = (uint32_t)(row * 128 + ((ch ^ (row & 7)) << 4));
            cpasync16(sA[st] + phys, Abase + (size_t)row * KP2 + koff0 + c * 64 + ch * 8);
        }
    };

    for (int t = 0; t < TT; t++) {
        // ===== GEMM phase: mh[z] tile = hs_tile @ Wres^T =====
        float acc[2][4][4];
        #pragma unroll
        for (int i = 0; i < 2; i++)
            #pragma unroll
            for (int j = 0; j < 4; j++)
                #pragma unroll
                for (int e = 0; e < 4; e++) acc[i][j][e] = 0.0f;

        loadA(0, 0);
        CP_COMMIT();
        for (int c = 0; c < BCH; c++) {
            if (c + 1 < BCH) loadA((c + 1) & 1, c + 1);
            CP_COMMIT();
            CP_WAIT1();
            __syncthreads();

            uint32_t a = sA[c & 1];
            uint32_t b = sBres + c * CHB;
            #pragma unroll
            for (int s = 0; s < 4; s++) {
                uint32_t af[2][4];
                #pragma unroll
                for (int i = 0; i < 2; i++) {
                    int row = wm * 32 + i * 16 + (lane & 15);
                    int ch  = 2 * s + (lane >> 4);
                    ldsm_x4(af[i][0], af[i][1], af[i][2], af[i][3],
                            a + row * 128 + ((ch ^ (row & 7)) << 4));
                }
                uint32_t bfm[2][4];
                #pragma unroll
                for (int j = 0; j < 2; j++) {
                    int row = wn * 32 + j * 16 + (lane & 7) + ((lane >> 4) << 3);
                    int ch  = 2 * s + ((lane >> 3) & 1);
                    ldsm_x4(bfm[j][0], bfm[j][1], bfm[j][2], bfm[j][3],
                            b + row * 128 + ((ch ^ (row & 7)) << 4));
                }
                #pragma unroll
                for (int i = 0; i < 2; i++)
                    #pragma unroll
                    for (int nj = 0; nj < 4; nj++)
                        mma_fp16(acc[i][nj][0], acc[i][nj][1], acc[i][nj][2], acc[i][nj][3],
                                 af[i][0], af[i][1], af[i][2], af[i][3],
                                 bfm[nj >> 1][(nj & 1) * 2], bfm[nj >> 1][(nj & 1) * 2 + 1]);
            }
            __syncthreads();
        }

        // epilogue -> mh[z] (still x1024 scaled; step divides)
        {
            int g = lane >> 2, t4 = lane & 3;
            #pragma unroll
            for (int i = 0; i < 2; i++)
                #pragma unroll
                for (int nj = 0; nj < 4; nj++) {
                    size_t row0 = (size_t)(y * 64 + wm * 32 + i * 16 + g);
                    size_t col  = (size_t)(x * 128 + wn * 32 + nj * 8 + 2 * t4);
                    *reinterpret_cast<float2*>(&mhz[row0 * HH + col]) =
                        make_float2(acc[i][nj][0], acc[i][nj][1]);
                    *reinterpret_cast<float2*>(&mhz[(row0 + 8) * HH + col]) =
                        make_float2(acc[i][nj][2], acc[i][nj][3]);
                }
        }
        grid_barrier();

        // ===== STEP phase: rows b0, b0+1 =====
        for (int r = 0; r < 2; r++) {
            int b = b0 + r;
            const float* pr = prem + ((size_t)b * TT + t) * HH;
            float p[4], m[4], bv[4];
            float s_mx2 = 0, s_mxm = 0, s_mxb = 0, s_m2 = 0, s_mb = 0, s_b2 = 0;
            #pragma unroll
            for (int j = 0; j < 4; j++) {
                int e = tid + j * 256;
                float mv = (__ldcv(&mh[(size_t)0 * BB * HH + (size_t)b * HH + e])
                          + __ldcv(&mh[(size_t)1 * BB * HH + (size_t)b * HH + e])
                          + __ldcv(&mh[(size_t)2 * BB * HH + (size_t)b * HH + e])
                          + __ldcv(&mh[(size_t)3 * BB * HH + (size_t)b * HH + e])) * ISC2;
                float pv = pr[e];
                float bb = bvec[e];
                m[j] = mv; p[j] = pv; bv[j] = bb;
                s_mx2 += pv * pv;  s_mxm += pv * mv;  s_mxb += pv * bb;
                s_m2  += mv * mv;  s_mb  += mv * bb;  s_b2  += bb * bb;
            }
            float vals[6] = { s_mx2, s_mxm, s_mxb, s_m2, s_mb, s_b2 };
            block_reduce8<6>(vals, redbuf);
            float mx2 = vals[0], mxm = vals[1], mxb = vals[2];
            float m2  = vals[3], mb  = vals[4], b2  = vals[5];

            float xn  = xn_arr[(size_t)b * TT + t];
            float mxn = fmaxf(sqrtf(mx2), EPSF);
            float fp  = tanhf(mxn / xn * artanh_clip(xn)) / mxn;
            float p2  = fp * fp * mx2;
            float pm  = fp * mxm;
            float pb  = fp * mxb;

            float hn  = hn_loc[r];
            float mhn = fmaxf(sqrtf(m2), EPSF);
            float fu  = tanhf(mhn / hn * artanh_clip(hn)) / mhn;
            float u2  = fu * fu * m2;
            float ub  = fu * mb;

            float den1 = fmaxf(1.0f + 2.0f * ub + u2 * b2, EPSF);
            float a1 = (1.0f + 2.0f * ub + b2) / den1;
            float c1 = (1.0f - u2) / den1;
            float hid2 = a1 * a1 * u2 + 2.0f * a1 * c1 * ub + c1 * c1 * b2;
            float ph   = a1 * fu * pm + c1 * pb;

            float den2 = fmaxf(1.0f + 2.0f * ph + p2 * hid2, EPSF);
            float q1 = (1.0f + 2.0f * ph + hid2) / den2;
            float q2 = (1.0f - p2) / den2;
            float s2 = q1 * q1 * p2 + q2 * q2 * hid2 + 2.0f * q1 * q2 * ph;
            float sn = fmaxf(sqrtf(s2), EPSF);
            float gg = artanh_clip(sn) / sn;

            float cp_ = q1 * fp;
            float cm  = q2 * a1 * fu;
            float cb  = q2 * c1;

            float v[4]; float s_v2 = 0.0f;
            #pragma unroll
            for (int j = 0; j < 4; j++) {
                float sv = cp_ * p[j] + cm * m[j] + cb * bv[j];
                float vv = tanhf(gg * sv);
                v[j] = vv; s_v2 += vv * vv;
            }
            float vv2[1] = { s_v2 };
            block_reduce8<1>(vv2, redbuf);
            float vn = fmaxf(sqrtf(vv2[0]), EPSF);
            float kk = tanhf(vn) / vn;

            __half* hrow = hs + (size_t)b * KP2;
            float* orow = out + (size_t)b * HH;
            #pragma unroll
            for (int j = 0; j < 4; j++) {
                int e = tid + j * 256;
                float hv = kk * v[j];
                float hvs = hv * XSC;
                __half hi = __float2half_rn(hvs);
                __half lo = __float2half_rn(hvs - __half2float(hi));
                hrow[e] = hi;
                hrow[EE + e] = lo;
                if (t == TT - 1) orow[e] = hv;
            }
            hn_loc[r] = fmaxf(tanhf(vn), EPSF);
        }
        grid_barrier();
    }
}

// ---------------- launch ----------------
extern "C" void kernel_launch(void* const* d_in, const int* in_sizes, int n_in,
                              void* d_out, int out_size)
{
    const float* inp  = (const float*)d_in[0];   // [B,T,E]
    const float* W_ih = (const float*)d_in[1];   // [E,H]
    const float* W_hh = (const float*)d_in[2];   // [H,H]
    const float* b_h  = (const float*)d_in[3];   // [H]
    float* out = (float*)d_out;                  // [B,H]

    __half *Xs, *WihT, *WhhT, *hs;
    float *prem, *mh, *xn;
    cudaGetSymbolAddress((void**)&Xs,   g_Xs);
    cudaGetSymbolAddress((void**)&WihT, g_WihT);
    cudaGetSymbolAddress((void**)&WhhT, g_WhhT);
    cudaGetSymbolAddress((void**)&hs,   g_hs);
    cudaGetSymbolAddress((void**)&prem, g_prem);
    cudaGetSymbolAddress((void**)&mh,   g_mh);
    cudaGetSymbolAddress((void**)&xn,   g_xn);

    const int SMEM_BIG = 3 * (128 + 128) * 128;            // 96 KB (3 stages)
    const int SMEM_REC = 8 * 128 * 128 + 2 * 64 * 128;     // 128KB + 16KB = 144 KB
    cudaFuncSetAttribute(big_gemm_kernel,
                         cudaFuncAttributeMaxDynamicSharedMemorySize, SMEM_BIG);
    cudaFuncSetAttribute(recurrence_kernel,
                         cudaFuncAttributeMaxDynamicSharedMemorySize, SMEM_REC);

    // init split hidden = 0
    {
        int n = (int)((size_t)BB * KP2 / 2);
        init_kernel<<<(n + 255) / 256, 256>>>((uint32_t*)hs);
    }

    // prep: weight splits + X split/norms
    {
        dim3 gw(HH / 32, HH / 32);
        splitW_kernel<<<gw, 256>>>(W_ih, WihT);
        splitW_kernel<<<gw, 256>>>(W_hh, WhhT);
        splitX_kernel<<<BB * TT, 256>>>(inp, Xs, xn);
    }

    // big GEMM: raw prem = Xs @ WihT^T  [32768, 1024] (fp16 2-seg)
    {
        dim3 grid(HH / 128, (BB * TT) / 128);
        big_gemm_kernel<<<grid, 256, SMEM_BIG>>>(Xs, WihT, prem);
    }

    // persistent recurrence: one kernel for all 128 steps
    recurrence_kernel<<<PK_NCTA, 256, SMEM_REC>>>(WhhT, prem, b_h, xn, hs, mh, out);
}

// round 10
// speedup vs baseline: 1.3572x; 1.1163x over previous
#include <cuda_runtime.h>
#include <cuda_bf16.h>
#include <cuda_fp16.h>
#include <math.h>
#include <stdint.h>

// ---------------- problem constants ----------------
#define BB   256      // batch
#define TT   128      // time steps
#define EE   1024     // input dim
#define HH   1024     // hidden dim
#define KP2  2048     // big-GEMM fp16 2-segment K'
#define KR   1024     // recurrence K (h hi-only fp16)
#define EPSF 1e-6f
#define XSC  32.0f    // pre-scale per side for fp16 (result /1024)
#define ISC2 (1.0f / (XSC * XSC))

// ---------------- scratch ----------------
__device__ __half g_Xs   [(size_t)BB * TT * KP2]; // X fp16 split [B*T, 2E] (hi|lo), x*32
__device__ __half g_WihT [(size_t)HH * KP2];      // W_ih^T fp16 [H, 2E] (hi|hi), W*32
__device__ __half g_WhhT [(size_t)HH * KR];       // W_hh^T fp16 [H, H] (hi), W*32
__device__ __half g_hs   [(size_t)BB * KR];       // h fp16 [B, H] (hi), h*32
__device__ float g_prem[(size_t)BB * TT * HH];    // RAW X@W_ih (true scale), all t
__device__ float g_mh  [4 * (size_t)BB * HH];     // 4 split-K partials (scaled x1024)
__device__ float g_xn  [(size_t)BB * TT];         // ||x_t|| per row (clamped)
__device__ unsigned g_bar_cnt = 0;
__device__ unsigned g_bar_gen = 0;

// ---------------- PTX helpers (sm_80-level) ----------------
__device__ __forceinline__ uint32_t smem_u32(const void* p) {
    uint32_t a;
    asm("{ .reg .u64 t; cvta.to.shared.u64 t, %1; cvt.u32.u64 %0, t; }" : "=r"(a) : "l"(p));
    return a;
}
__device__ __forceinline__ void cpasync16(uint32_t s, const void* g) {
    asm volatile("cp.async.cg.shared.global [%0], [%1], 16;" :: "r"(s), "l"(g));
}
#define CP_COMMIT() asm volatile("cp.async.commit_group;" ::: "memory")
#define CP_WAIT1()  asm volatile("cp.async.wait_group 1;" ::: "memory")
#define CP_WAIT2()  asm volatile("cp.async.wait_group 2;" ::: "memory")

__device__ __forceinline__ void ldsm_x4(uint32_t& r0, uint32_t& r1, uint32_t& r2, uint32_t& r3,
                                        uint32_t addr) {
    asm volatile("ldmatrix.sync.aligned.m8n8.x4.shared.b16 {%0,%1,%2,%3}, [%4];"
                 : "=r"(r0), "=r"(r1), "=r"(r2), "=r"(r3) : "r"(addr));
}
__device__ __forceinline__ void mma_fp16(float& d0, float& d1, float& d2, float& d3,
                                         uint32_t a0, uint32_t a1, uint32_t a2, uint32_t a3,
                                         uint32_t b0, uint32_t b1) {
    asm volatile(
        "mma.sync.aligned.m16n8k16.row.col.f32.f16.f16.f32 "
        "{%0,%1,%2,%3}, {%4,%5,%6,%7}, {%8,%9}, {%0,%1,%2,%3};"
        : "+f"(d0), "+f"(d1), "+f"(d2), "+f"(d3)
        : "r"(a0), "r"(a1), "r"(a2), "r"(a3), "r"(b0), "r"(b1));
}

// ---------------- init ----------------
__global__ void init_kernel(uint32_t* hs_u32) {
    int i = blockIdx.x * blockDim.x + threadIdx.x;
    if (i < (int)((size_t)BB * KR / 2)) hs_u32[i] = 0u;
}

// ---------------- splitX: fp16 hi/lo of 32*x, plus ||x|| ----------------
__global__ __launch_bounds__(256) void splitX_kernel(const float* __restrict__ X,
                                                     __half* __restrict__ Xs,
                                                     float* __restrict__ xn) {
    __shared__ float sh[8];
    size_t r = blockIdx.x;
    const float* x = X + r * EE;
    __half* row = Xs + r * KP2;
    float x2 = 0.0f;
    #pragma unroll
    for (int j = 0; j < 4; j++) {
        int e = threadIdx.x + j * 256;
        float v = x[e];
        x2 += v * v;
        float vs = v * XSC;
        __half hi = __float2half_rn(vs);
        __half lo = __float2half_rn(vs - __half2float(hi));
        row[e] = hi;
        row[EE + e] = lo;
    }
    #pragma unroll
    for (int o = 16; o > 0; o >>= 1) x2 += __shfl_down_sync(0xffffffffu, x2, o);
    if ((threadIdx.x & 31) == 0) sh[threadIdx.x >> 5] = x2;
    __syncthreads();
    if (threadIdx.x == 0) {
        float s = 0.0f;
        #pragma unroll
        for (int w = 0; w < 8; w++) s += sh[w];
        xn[r] = fmaxf(sqrtf(s), EPSF);
    }
}

// ---------------- W_ih [K,N] -> fp16 Wt [N, 2K] (hi|hi), scaled, transposed ----
__global__ __launch_bounds__(256) void splitWih_kernel(const float* __restrict__ W,
                                                       __half* __restrict__ Wt) {
    __shared__ float tile[32][33];
    int n0 = blockIdx.x * 32;
    int k0 = blockIdx.y * 32;
    int tx = threadIdx.x & 31;
    int ty = threadIdx.x >> 5;
    #pragma unroll
    for (int i = 0; i < 32; i += 8)
        tile[ty + i][tx] = W[(size_t)(k0 + ty + i) * HH + n0 + tx];
    __syncthreads();
    #pragma unroll
    for (int i = 0; i < 32; i += 8) {
        float v = tile[tx][ty + i] * XSC;
        int n = n0 + ty + i;
        int k = k0 + tx;
        __half hi = __float2half_rn(v);
        __half* row = Wt + (size_t)n * KP2;
        row[k] = hi;            // seg 0 (pairs with X-hi)
        row[EE + k] = hi;       // seg 1 (pairs with X-lo)
    }
}

// ---------------- W_hh [K,N] -> fp16 Wt [N, K] (hi only), scaled, transposed ----
__global__ __launch_bounds__(256) void splitWhh_kernel(const float* __restrict__ W,
                                                       __half* __restrict__ Wt) {
    __shared__ float tile[32][33];
    int n0 = blockIdx.x * 32;
    int k0 = blockIdx.y * 32;
    int tx = threadIdx.x & 31;
    int ty = threadIdx.x >> 5;
    #pragma unroll
    for (int i = 0; i < 32; i += 8)
        tile[ty + i][tx] = W[(size_t)(k0 + ty + i) * HH + n0 + tx];
    __syncthreads();
    #pragma unroll
    for (int i = 0; i < 32; i += 8) {
        float v = tile[tx][ty + i] * XSC;
        int n = n0 + ty + i;
        int k = k0 + tx;
        Wt[(size_t)n * KR + k] = __float2half_rn(v);
    }
}

// ---------------- big GEMM (fp16, 2-seg): prem_raw = Xs @ WihT^T / 1024 --------
// BM=BN=128, 256 thr (2x4 warps), 3-stage cp.async, 32 chunks of 64.
__global__ void __launch_bounds__(256, 2)
big_gemm_kernel(const __half* __restrict__ A,
                const __half* __restrict__ B,
                float* __restrict__ C)
{
    constexpr int ABYTES = 128 * 128, BBYTES = 128 * 128;
    constexpr int NCH = KP2 / 64;     // 32
    extern __shared__ char smem[];
    uint32_t sbase = smem_u32(smem);
    uint32_t sA[3], sB[3];
    #pragma unroll
    for (int s = 0; s < 3; s++) {
        sA[s] = sbase + s * (ABYTES + BBYTES);
        sB[s] = sA[s] + ABYTES;
    }

    int tid  = threadIdx.x;
    int warp = tid >> 5;
    int lane = tid & 31;
    int wm = warp & 1;         // WARP_M = 64, MT = 4
    int wn = warp >> 1;        // WARP_N = 32, NT8 = 4

    size_t rowTile = (size_t)blockIdx.y * 128;
    size_t colTile = (size_t)blockIdx.x * 128;
    const __half* Abase = A + rowTile * KP2;
    const __half* Bbase = B + colTile * KP2;

    float acc[4][4][4];
    #pragma unroll
    for (int i = 0; i < 4; i++)
        #pragma unroll
        for (int j = 0; j < 4; j++)
            #pragma unroll
            for (int e = 0; e < 4; e++) acc[i][j][e] = 0.0f;

    auto load_stage = [&](int st, int c) {
        const __half* Ag = Abase + (size_t)c * 64;
        const __half* Bg = Bbase + (size_t)c * 64;
        #pragma unroll
        for (int u = tid; u < 128 * 8; u += 256) {
            int row = u >> 3, ch = u & 7;
            uint32_t phys = (uint32_t)(row * 128 + ((ch ^ (row & 7)) << 4));
            cpasync16(sA[st] + phys, Ag + (size_t)row * KP2 + ch * 8);
        }
        #pragma unroll
        for (int u = tid; u < 128 * 8; u += 256) {
            int row = u >> 3, ch = u & 7;
            uint32_t phys = (uint32_t)(row * 128 + ((ch ^ (row & 7)) << 4));
            cpasync16(sB[st] + phys, Bg + (size_t)row * KP2 + ch * 8);
        }
    };

    load_stage(0, 0); CP_COMMIT();
    load_stage(1, 1); CP_COMMIT();

    int st = 0;
    for (int c = 0; c < NCH; c++) {
        if (c + 2 < NCH) load_stage((st + 2) % 3, c + 2);
        CP_COMMIT();
        CP_WAIT2();
        __syncthreads();

        uint32_t a = sA[st], b = sB[st];
        #pragma unroll
        for (int s = 0; s < 4; s++) {
            uint32_t af[4][4];
            #pragma unroll
            for (int i = 0; i < 4; i++) {
                int row = wm * 64 + i * 16 + (lane & 15);
                int ch  = 2 * s + (lane >> 4);
                ldsm_x4(af[i][0], af[i][1], af[i][2], af[i][3],
                        a + row * 128 + ((ch ^ (row & 7)) << 4));
            }
            uint32_t bfm[2][4];
            #pragma unroll
            for (int j = 0; j < 2; j++) {
                int row = wn * 32 + j * 16 + (lane & 7) + ((lane >> 4) << 3);
                int ch  = 2 * s + ((lane >> 3) & 1);
                ldsm_x4(bfm[j][0], bfm[j][1], bfm[j][2], bfm[j][3],
                        b + row * 128 + ((ch ^ (row & 7)) << 4));
            }
            #pragma unroll
            for (int i = 0; i < 4; i++)
                #pragma unroll
                for (int nj = 0; nj < 4; nj++)
                    mma_fp16(acc[i][nj][0], acc[i][nj][1], acc[i][nj][2], acc[i][nj][3],
                             af[i][0], af[i][1], af[i][2], af[i][3],
                             bfm[nj >> 1][(nj & 1) * 2], bfm[nj >> 1][(nj & 1) * 2 + 1]);
        }
        __syncthreads();
        st = (st + 1) % 3;
    }

    int g = lane >> 2, t4 = lane & 3;
    #pragma unroll
    for (int i = 0; i < 4; i++)
        #pragma unroll
        for (int nj = 0; nj < 4; nj++) {
            size_t row0 = rowTile + wm * 64 + i * 16 + g;
            size_t col  = colTile + wn * 32 + nj * 8 + 2 * t4;
            *reinterpret_cast<float2*>(&C[row0 * HH + col]) =
                make_float2(acc[i][nj][0] * ISC2, acc[i][nj][1] * ISC2);
            *reinterpret_cast<float2*>(&C[(row0 + 8) * HH + col]) =
                make_float2(acc[i][nj][2] * ISC2, acc[i][nj][3] * ISC2);
        }
}

// ---------------- helpers for step math ----------------
template <int NV>
__device__ __forceinline__ void block_reduce8(float* vals, float* shbuf /* NV*8 */) {
    __syncthreads();
    #pragma unroll
    for (int v = 0; v < NV; v++) {
        float x = vals[v];
        #pragma unroll
        for (int o = 16; o > 0; o >>= 1) x += __shfl_down_sync(0xffffffffu, x, o);
        if ((threadIdx.x & 31) == 0) shbuf[v * 8 + (threadIdx.x >> 5)] = x;
    }
    __syncthreads();
    #pragma unroll
    for (int v = 0; v < NV; v++) {
        float s = 0.0f;
        #pragma unroll
        for (int w = 0; w < 8; w++) s += shbuf[v * 8 + w];
        vals[v] = s;
    }
}
__device__ __forceinline__ float artanh_clip(float x) {
    return atanhf(fminf(x, 1.0f - 1e-6f));
}

// ---------------- persistent recurrence kernel (256 thr, 128 CTAs) ----------
#define PK_NCTA 128

__device__ __forceinline__ void grid_barrier() {
    __threadfence();
    __syncthreads();
    if (threadIdx.x == 0) {
        unsigned gen = *(volatile unsigned*)&g_bar_gen;
        unsigned old = atomicAdd(&g_bar_cnt, 1u);
        if (old == PK_NCTA - 1) {
            g_bar_cnt = 0;
            __threadfence();
            atomicExch(&g_bar_gen, gen + 1);
        } else {
            while (*(volatile unsigned*)&g_bar_gen == gen) { }
        }
        __threadfence();
    }
    __syncthreads();
}

__global__ void __launch_bounds__(256, 1)
recurrence_kernel(const __half* __restrict__ W,        // WhhT [H, H] fp16 hi
                  const float* __restrict__ prem,      // raw [B,T,H]
                  const float* __restrict__ bvec,      // b_h
                  const float* __restrict__ xn_arr,    // [B*T]
                  __half* __restrict__ hs,             // [B, H] fp16 hi
                  float* __restrict__ mh,              // [4][B][H] (x1024 scaled)
                  float* __restrict__ out)             // [B,H]
{
    constexpr int BCH = 4;                  // 4 chunks of 64 = 256 K-quarter
    constexpr int CHB = 128 * 128;          // bytes per resident-B chunk
    extern __shared__ char smem[];
    __shared__ float redbuf[6 * 8];
    uint32_t sbase = smem_u32(smem);
    uint32_t sBres = sbase;                 // 64 KB resident B
    uint32_t sA[2] = { sbase + BCH * CHB, sbase + BCH * CHB + 64 * 128 };

    int bid  = blockIdx.x;
    int z = bid & 3;                        // K quarter (256 wide)
    int x = (bid >> 2) & 7;                 // col tile (128 wide)
    int y = bid >> 5;                       // row tile (64 tall)
    int tid  = threadIdx.x;
    int warp = tid >> 5;
    int lane = tid & 31;
    int wm = warp & 1;                      // WARP_M = 32, MT = 2
    int wn = warp >> 1;                     // WARP_N = 32, NT8 = 4

    // resident B: rows [x*128, +128) of W, K [z*256, +256)
    {
        const __half* Wb = W + (size_t)(x * 128) * KR + (size_t)z * 256;
        for (int u = tid; u < BCH * 128 * 8; u += 256) {
            int c   = u / (128 * 8);
            int rem = u - c * (128 * 8);
            int row = rem >> 3, ch = rem & 7;
            uint32_t phys = (uint32_t)(c * CHB + row * 128 + ((ch ^ (row & 7)) << 4));
            cpasync16(sBres + phys, Wb + (size_t)row * KR + c * 64 + ch * 8);
        }
        CP_COMMIT();
    }

    const __half* Abase = hs + (size_t)(y * 64) * KR;
    float* mhz = mh + (size_t)z * BB * HH;
    int koff0 = z * 256;

    float hn_loc[2] = { EPSF, EPSF };
    int b0 = bid * 2;

    auto loadA = [&](int st, int c) {       // A chunk: 64 rows x 64 k
        #pragma unroll
        for (int u = tid; u < 64 * 8; u += 256) {
            int row = u >> 3, ch = u & 7;
            uint32_t phys = (uint32_t)(row * 128 + ((ch ^ (row & 7)) << 4));
            cpasync16(sA[st] + phys, Abase + (size_t)row * KR + koff0 + c * 64 + ch * 8);
        }
    };

    for (int t = 0; t < TT; t++) {
        // ===== GEMM phase: mh[z] tile = hs_tile @ Wres^T =====
        float acc[2][4][4];
        #pragma unroll
        for (int i = 0; i < 2; i++)
            #pragma unroll
            for (int j = 0; j < 4; j++)
                #pragma unroll
                for (int e = 0; e < 4; e++) acc[i][j][e] = 0.0f;

        loadA(0, 0);
        CP_COMMIT();
        for (int c = 0; c < BCH; c++) {
            if (c + 1 < BCH) loadA((c + 1) & 1, c + 1);
            CP_COMMIT();
            CP_WAIT1();
            __syncthreads();

            uint32_t a = sA[c & 1];
            uint32_t b = sBres + c * CHB;
            #pragma unroll
            for (int s = 0; s < 4; s++) {
                uint32_t af[2][4];
                #pragma unroll
                for (int i = 0; i < 2; i++) {
                    int row = wm * 32 + i * 16 + (lane & 15);
                    int ch  = 2 * s + (lane >> 4);
                    ldsm_x4(af[i][0], af[i][1], af[i][2], af[i][3],
                            a + row * 128 + ((ch ^ (row & 7)) << 4));
                }
                uint32_t bfm[2][4];
                #pragma unroll
                for (int j = 0; j < 2; j++) {
                    int row = wn * 32 + j * 16 + (lane & 7) + ((lane >> 4) << 3);
                    int ch  = 2 * s + ((lane >> 3) & 1);
                    ldsm_x4(bfm[j][0], bfm[j][1], bfm[j][2], bfm[j][3],
                            b + row * 128 + ((ch ^ (row & 7)) << 4));
                }
                #pragma unroll
                for (int i = 0; i < 2; i++)
                    #pragma unroll
                    for (int nj = 0; nj < 4; nj++)
                        mma_fp16(acc[i][nj][0], acc[i][nj][1], acc[i][nj][2], acc[i][nj][3],
                                 af[i][0], af[i][1], af[i][2], af[i][3],
                                 bfm[nj >> 1][(nj & 1) * 2], bfm[nj >> 1][(nj & 1) * 2 + 1]);
            }
            __syncthreads();
        }

        // epilogue -> mh[z] (x1024 scaled; step divides)
        {
            int g = lane >> 2, t4 = lane & 3;
            #pragma unroll
            for (int i = 0; i < 2; i++)
                #pragma unroll
                for (int nj = 0; nj < 4; nj++) {
                    size_t row0 = (size_t)(y * 64 + wm * 32 + i * 16 + g);
                    size_t col  = (size_t)(x * 128 + wn * 32 + nj * 8 + 2 * t4);
                    *reinterpret_cast<float2*>(&mhz[row0 * HH + col]) =
                        make_float2(acc[i][nj][0], acc[i][nj][1]);
                    *reinterpret_cast<float2*>(&mhz[(row0 + 8) * HH + col]) =
                        make_float2(acc[i][nj][2], acc[i][nj][3]);
                }
        }
        grid_barrier();

        // ===== STEP phase: rows b0, b0+1 =====
        for (int r = 0; r < 2; r++) {
            int b = b0 + r;
            const float* pr = prem + ((size_t)b * TT + t) * HH;
            float p[4], m[4], bv[4];
            float s_mx2 = 0, s_mxm = 0, s_mxb = 0, s_m2 = 0, s_mb = 0, s_b2 = 0;
            #pragma unroll
            for (int j = 0; j < 4; j++) {
                int e = tid + j * 256;
                float mv = (__ldcv(&mh[(size_t)0 * BB * HH + (size_t)b * HH + e])
                          + __ldcv(&mh[(size_t)1 * BB * HH + (size_t)b * HH + e])
                          + __ldcv(&mh[(size_t)2 * BB * HH + (size_t)b * HH + e])
                          + __ldcv(&mh[(size_t)3 * BB * HH + (size_t)b * HH + e])) * ISC2;
                float pv = pr[e];
                float bb = bvec[e];
                m[j] = mv; p[j] = pv; bv[j] = bb;
                s_mx2 += pv * pv;  s_mxm += pv * mv;  s_mxb += pv * bb;
                s_m2  += mv * mv;  s_mb  += mv * bb;  s_b2  += bb * bb;
            }
            float vals[6] = { s_mx2, s_mxm, s_mxb, s_m2, s_mb, s_b2 };
            block_reduce8<6>(vals, redbuf);
            float mx2 = vals[0], mxm = vals[1], mxb = vals[2];
            float m2  = vals[3], mb  = vals[4], b2  = vals[5];

            float xn  = xn_arr[(size_t)b * TT + t];
            float mxn = fmaxf(sqrtf(mx2), EPSF);
            float fp  = tanhf(mxn / xn * artanh_clip(xn)) / mxn;
            float p2  = fp * fp * mx2;
            float pm  = fp * mxm;
            float pb  = fp * mxb;

            float hn  = hn_loc[r];
            float mhn = fmaxf(sqrtf(m2), EPSF);
            float fu  = tanhf(mhn / hn * artanh_clip(hn)) / mhn;
            float u2  = fu * fu * m2;
            float ub  = fu * mb;

            float den1 = fmaxf(1.0f + 2.0f * ub + u2 * b2, EPSF);
            float a1 = (1.0f + 2.0f * ub + b2) / den1;
            float c1 = (1.0f - u2) / den1;
            float hid2 = a1 * a1 * u2 + 2.0f * a1 * c1 * ub + c1 * c1 * b2;
            float ph   = a1 * fu * pm + c1 * pb;

            float den2 = fmaxf(1.0f + 2.0f * ph + p2 * hid2, EPSF);
            float q1 = (1.0f + 2.0f * ph + hid2) / den2;
            float q2 = (1.0f - p2) / den2;
            float s2 = q1 * q1 * p2 + q2 * q2 * hid2 + 2.0f * q1 * q2 * ph;
            float sn = fmaxf(sqrtf(s2), EPSF);
            float gg = artanh_clip(sn) / sn;

            float cp_ = q1 * fp;
            float cm  = q2 * a1 * fu;
            float cb  = q2 * c1;

            float v[4]; float s_v2 = 0.0f;
            #pragma unroll
            for (int j = 0; j < 4; j++) {
                float sv = cp_ * p[j] + cm * m[j] + cb * bv[j];
                float vv = tanhf(gg * sv);
                v[j] = vv; s_v2 += vv * vv;
            }
            float vv2[1] = { s_v2 };
            block_reduce8<1>(vv2, redbuf);
            float vn = fmaxf(sqrtf(vv2[0]), EPSF);
            float kk = tanhf(vn) / vn;

            __half* hrow = hs + (size_t)b * KR;
            float* orow = out + (size_t)b * HH;
            #pragma unroll
            for (int j = 0; j < 4; j++) {
                int e = tid + j * 256;
                float hv = kk * v[j];
                hrow[e] = __float2half_rn(hv * XSC);
                if (t == TT - 1) orow[e] = hv;
            }
            hn_loc[r] = fmaxf(tanhf(vn), EPSF);
        }
        grid_barrier();
    }
}

// ---------------- launch ----------------
extern "C" void kernel_launch(void* const* d_in, const int* in_sizes, int n_in,
                              void* d_out, int out_size)
{
    const float* inp  = (const float*)d_in[0];   // [B,T,E]
    const float* W_ih = (const float*)d_in[1];   // [E,H]
    const float* W_hh = (const float*)d_in[2];   // [H,H]
    const float* b_h  = (const float*)d_in[3];   // [H]
    float* out = (float*)d_out;                  // [B,H]

    __half *Xs, *WihT, *WhhT, *hs;
    float *prem, *mh, *xn;
    cudaGetSymbolAddress((void**)&Xs,   g_Xs);
    cudaGetSymbolAddress((void**)&WihT, g_WihT);
    cudaGetSymbolAddress((void**)&WhhT, g_WhhT);
    cudaGetSymbolAddress((void**)&hs,   g_hs);
    cudaGetSymbolAddress((void**)&prem, g_prem);
    cudaGetSymbolAddress((void**)&mh,   g_mh);
    cudaGetSymbolAddress((void**)&xn,   g_xn);

    const int SMEM_BIG = 3 * (128 + 128) * 128;            // 96 KB (3 stages)
    const int SMEM_REC = 4 * 128 * 128 + 2 * 64 * 128;     // 64KB + 16KB = 80 KB
    cudaFuncSetAttribute(big_gemm_kernel,
                         cudaFuncAttributeMaxDynamicSharedMemorySize, SMEM_BIG);
    cudaFuncSetAttribute(recurrence_kernel,
                         cudaFuncAttributeMaxDynamicSharedMemorySize, SMEM_REC);

    // init hidden = 0
    {
        int n = (int)((size_t)BB * KR / 2);
        init_kernel<<<(n + 255) / 256, 256>>>((uint32_t*)hs);
    }

    // prep: weight splits + X split/norms
    {
        dim3 gw(HH / 32, HH / 32);
        splitWih_kernel<<<gw, 256>>>(W_ih, WihT);
        splitWhh_kernel<<<gw, 256>>>(W_hh, WhhT);
        splitX_kernel<<<BB * TT, 256>>>(inp, Xs, xn);
    }

    // big GEMM: raw prem = Xs @ WihT^T  [32768, 1024] (fp16 2-seg)
    {
        dim3 grid(HH / 128, (BB * TT) / 128);
        big_gemm_kernel<<<grid, 256, SMEM_BIG>>>(Xs, WihT, prem);
    }

    // persistent recurrence: one kernel for all 128 steps
    recurrence_kernel<<<PK_NCTA, 256, SMEM_REC>>>(WhhT, prem, b_h, xn, hs, mh, out);
}

// round 11
// speedup vs baseline: 1.4940x; 1.1008x over previous
#include <cuda_runtime.h>
#include <cuda_bf16.h>
#include <cuda_fp16.h>
#include <math.h>
#include <stdint.h>

// ---------------- problem constants ----------------
#define BB   256      // batch
#define TT   128      // time steps
#define EE   1024     // input dim
#define HH   1024     // hidden dim
#define KP2  2048     // big-GEMM fp16 2-segment K'
#define KR   1024     // recurrence K (h hi-only fp16)
#define EPSF 1e-6f
#define XSC  32.0f    // pre-scale per side for fp16 (result /1024)
#define ISC2 (1.0f / (XSC * XSC))

// ---------------- scratch ----------------
__device__ __half g_Xs   [(size_t)BB * TT * KP2]; // X fp16 split [B*T, 2E] (hi|lo), x*32
__device__ __half g_WihT [(size_t)HH * KP2];      // W_ih^T fp16 [H, 2E] (hi|hi), W*32
__device__ __half g_WhhT [(size_t)HH * KR];       // W_hh^T fp16 [H, H] (hi), W*32
__device__ __half g_hs   [(size_t)BB * KR];       // h fp16 [B, H] (hi), h*32
__device__ float g_prem[(size_t)BB * TT * HH];    // RAW X@W_ih (true scale), all t
__device__ float g_mh  [2 * (size_t)BB * HH];     // 2 split-K partials (scaled x1024)
__device__ float g_xn  [(size_t)BB * TT];         // ||x_t|| per row (clamped)
// per-group barriers (8 groups, cache-line separated)
__device__ unsigned g_gcnt[8 * 32];
__device__ unsigned g_ggen[8 * 32];

// ---------------- PTX helpers (sm_80-level) ----------------
__device__ __forceinline__ uint32_t smem_u32(const void* p) {
    uint32_t a;
    asm("{ .reg .u64 t; cvta.to.shared.u64 t, %1; cvt.u32.u64 %0, t; }" : "=r"(a) : "l"(p));
    return a;
}
__device__ __forceinline__ void cpasync16(uint32_t s, const void* g) {
    asm volatile("cp.async.cg.shared.global [%0], [%1], 16;" :: "r"(s), "l"(g));
}
#define CP_COMMIT() asm volatile("cp.async.commit_group;" ::: "memory")
#define CP_WAIT1()  asm volatile("cp.async.wait_group 1;" ::: "memory")
#define CP_WAIT2()  asm volatile("cp.async.wait_group 2;" ::: "memory")

__device__ __forceinline__ void ldsm_x4(uint32_t& r0, uint32_t& r1, uint32_t& r2, uint32_t& r3,
                                        uint32_t addr) {
    asm volatile("ldmatrix.sync.aligned.m8n8.x4.shared.b16 {%0,%1,%2,%3}, [%4];"
                 : "=r"(r0), "=r"(r1), "=r"(r2), "=r"(r3) : "r"(addr));
}
__device__ __forceinline__ void mma_fp16(float& d0, float& d1, float& d2, float& d3,
                                         uint32_t a0, uint32_t a1, uint32_t a2, uint32_t a3,
                                         uint32_t b0, uint32_t b1) {
    asm volatile(
        "mma.sync.aligned.m16n8k16.row.col.f32.f16.f16.f32 "
        "{%0,%1,%2,%3}, {%4,%5,%6,%7}, {%8,%9}, {%0,%1,%2,%3};"
        : "+f"(d0), "+f"(d1), "+f"(d2), "+f"(d3)
        : "r"(a0), "r"(a1), "r"(a2), "r"(a3), "r"(b0), "r"(b1));
}

// ---------------- init ----------------
__global__ void init_kernel(uint32_t* hs_u32) {
    int i = blockIdx.x * blockDim.x + threadIdx.x;
    if (i < (int)((size_t)BB * KR / 2)) hs_u32[i] = 0u;
}

// ---------------- splitX: fp16 hi/lo of 32*x, plus ||x|| ----------------
__global__ __launch_bounds__(256) void splitX_kernel(const float* __restrict__ X,
                                                     __half* __restrict__ Xs,
                                                     float* __restrict__ xn) {
    __shared__ float sh[8];
    size_t r = blockIdx.x;
    const float* x = X + r * EE;
    __half* row = Xs + r * KP2;
    float x2 = 0.0f;
    #pragma unroll
    for (int j = 0; j < 4; j++) {
        int e = threadIdx.x + j * 256;
        float v = x[e];
        x2 += v * v;
        float vs = v * XSC;
        __half hi = __float2half_rn(vs);
        __half lo = __float2half_rn(vs - __half2float(hi));
        row[e] = hi;
        row[EE + e] = lo;
    }
    #pragma unroll
    for (int o = 16; o > 0; o >>= 1) x2 += __shfl_down_sync(0xffffffffu, x2, o);
    if ((threadIdx.x & 31) == 0) sh[threadIdx.x >> 5] = x2;
    __syncthreads();
    if (threadIdx.x == 0) {
        float s = 0.0f;
        #pragma unroll
        for (int w = 0; w < 8; w++) s += sh[w];
        xn[r] = fmaxf(sqrtf(s), EPSF);
    }
}

// ---------------- W_ih [K,N] -> fp16 Wt [N, 2K] (hi|hi), scaled, transposed ----
__global__ __launch_bounds__(256) void splitWih_kernel(const float* __restrict__ W,
                                                       __half* __restrict__ Wt) {
    __shared__ float tile[32][33];
    int n0 = blockIdx.x * 32;
    int k0 = blockIdx.y * 32;
    int tx = threadIdx.x & 31;
    int ty = threadIdx.x >> 5;
    #pragma unroll
    for (int i = 0; i < 32; i += 8)
        tile[ty + i][tx] = W[(size_t)(k0 + ty + i) * HH + n0 + tx];
    __syncthreads();
    #pragma unroll
    for (int i = 0; i < 32; i += 8) {
        float v = tile[tx][ty + i] * XSC;
        int n = n0 + ty + i;
        int k = k0 + tx;
        __half hi = __float2half_rn(v);
        __half* row = Wt + (size_t)n * KP2;
        row[k] = hi;
        row[EE + k] = hi;
    }
}

// ---------------- W_hh [K,N] -> fp16 Wt [N, K] (hi only), scaled, transposed ----
__global__ __launch_bounds__(256) void splitWhh_kernel(const float* __restrict__ W,
                                                       __half* __restrict__ Wt) {
    __shared__ float tile[32][33];
    int n0 = blockIdx.x * 32;
    int k0 = blockIdx.y * 32;
    int tx = threadIdx.x & 31;
    int ty = threadIdx.x >> 5;
    #pragma unroll
    for (int i = 0; i < 32; i += 8)
        tile[ty + i][tx] = W[(size_t)(k0 + ty + i) * HH + n0 + tx];
    __syncthreads();
    #pragma unroll
    for (int i = 0; i < 32; i += 8) {
        float v = tile[tx][ty + i] * XSC;
        int n = n0 + ty + i;
        int k = k0 + tx;
        Wt[(size_t)n * KR + k] = __float2half_rn(v);
    }
}

// ---------------- big GEMM (fp16, 2-seg): prem_raw = Xs @ WihT^T / 1024 --------
__global__ void __launch_bounds__(256, 2)
big_gemm_kernel(const __half* __restrict__ A,
                const __half* __restrict__ B,
                float* __restrict__ C)
{
    constexpr int ABYTES = 128 * 128, BBYTES = 128 * 128;
    constexpr int NCH = KP2 / 64;     // 32
    extern __shared__ char smem[];
    uint32_t sbase = smem_u32(smem);
    uint32_t sA[3], sB[3];
    #pragma unroll
    for (int s = 0; s < 3; s++) {
        sA[s] = sbase + s * (ABYTES + BBYTES);
        sB[s] = sA[s] + ABYTES;
    }

    int tid  = threadIdx.x;
    int warp = tid >> 5;
    int lane = tid & 31;
    int wm = warp & 1;
    int wn = warp >> 1;

    size_t rowTile = (size_t)blockIdx.y * 128;
    size_t colTile = (size_t)blockIdx.x * 128;
    const __half* Abase = A + rowTile * KP2;
    const __half* Bbase = B + colTile * KP2;

    float acc[4][4][4];
    #pragma unroll
    for (int i = 0; i < 4; i++)
        #pragma unroll
        for (int j = 0; j < 4; j++)
            #pragma unroll
            for (int e = 0; e < 4; e++) acc[i][j][e] = 0.0f;

    auto load_stage = [&](int st, int c) {
        const __half* Ag = Abase + (size_t)c * 64;
        const __half* Bg = Bbase + (size_t)c * 64;
        #pragma unroll
        for (int u = tid; u < 128 * 8; u += 256) {
            int row = u >> 3, ch = u & 7;
            uint32_t phys = (uint32_t)(row * 128 + ((ch ^ (row & 7)) << 4));
            cpasync16(sA[st] + phys, Ag + (size_t)row * KP2 + ch * 8);
        }
        #pragma unroll
        for (int u = tid; u < 128 * 8; u += 256) {
            int row = u >> 3, ch = u & 7;
            uint32_t phys = (uint32_t)(row * 128 + ((ch ^ (row & 7)) << 4));
            cpasync16(sB[st] + phys, Bg + (size_t)row * KP2 + ch * 8);
        }
    };

    load_stage(0, 0); CP_COMMIT();
    load_stage(1, 1); CP_COMMIT();

    int st = 0;
    for (int c = 0; c < NCH; c++) {
        if (c + 2 < NCH) load_stage((st + 2) % 3, c + 2);
        CP_COMMIT();
        CP_WAIT2();
        __syncthreads();

        uint32_t a = sA[st], b = sB[st];
        #pragma unroll
        for (int s = 0; s < 4; s++) {
            uint32_t af[4][4];
            #pragma unroll
            for (int i = 0; i < 4; i++) {
                int row = wm * 64 + i * 16 + (lane & 15);
                int ch  = 2 * s + (lane >> 4);
                ldsm_x4(af[i][0], af[i][1], af[i][2], af[i][3],
                        a + row * 128 + ((ch ^ (row & 7)) << 4));
            }
            uint32_t bfm[2][4];
            #pragma unroll
            for (int j = 0; j < 2; j++) {
                int row = wn * 32 + j * 16 + (lane & 7) + ((lane >> 4) << 3);
                int ch  = 2 * s + ((lane >> 3) & 1);
                ldsm_x4(bfm[j][0], bfm[j][1], bfm[j][2], bfm[j][3],
                        b + row * 128 + ((ch ^ (row & 7)) << 4));
            }
            #pragma unroll
            for (int i = 0; i < 4; i++)
                #pragma unroll
                for (int nj = 0; nj < 4; nj++)
                    mma_fp16(acc[i][nj][0], acc[i][nj][1], acc[i][nj][2], acc[i][nj][3],
                             af[i][0], af[i][1], af[i][2], af[i][3],
                             bfm[nj >> 1][(nj & 1) * 2], bfm[nj >> 1][(nj & 1) * 2 + 1]);
        }
        __syncthreads();
        st = (st + 1) % 3;
    }

    int g = lane >> 2, t4 = lane & 3;
    #pragma unroll
    for (int i = 0; i < 4; i++)
        #pragma unroll
        for (int nj = 0; nj < 4; nj++) {
            size_t row0 = rowTile + wm * 64 + i * 16 + g;
            size_t col  = colTile + wn * 32 + nj * 8 + 2 * t4;
            *reinterpret_cast<float2*>(&C[row0 * HH + col]) =
                make_float2(acc[i][nj][0] * ISC2, acc[i][nj][1] * ISC2);
            *reinterpret_cast<float2*>(&C[(row0 + 8) * HH + col]) =
                make_float2(acc[i][nj][2] * ISC2, acc[i][nj][3] * ISC2);
        }
}

// ---------------- helpers for step math ----------------
template <int NV>
__device__ __forceinline__ void block_reduce8(float* vals, float* shbuf /* NV*8 */) {
    __syncthreads();
    #pragma unroll
    for (int v = 0; v < NV; v++) {
        float x = vals[v];
        #pragma unroll
        for (int o = 16; o > 0; o >>= 1) x += __shfl_down_sync(0xffffffffu, x, o);
        if ((threadIdx.x & 31) == 0) shbuf[v * 8 + (threadIdx.x >> 5)] = x;
    }
    __syncthreads();
    #pragma unroll
    for (int v = 0; v < NV; v++) {
        float s = 0.0f;
        #pragma unroll
        for (int w = 0; w < 8; w++) s += shbuf[v * 8 + w];
        vals[v] = s;
    }
}
__device__ __forceinline__ float artanh_clip(float x) {
    return atanhf(fminf(x, 1.0f - 1e-6f));
}

// ---------------- persistent recurrence kernel (256 thr, 128 CTAs) ----------
// Grid decode: y = bid>>4 (row band of 32), rem = bid&15, x = rem>>1 (col tile
// of 128), z = rem&1 (K half of 512). Only the 16 CTAs of a y-group couple.
#define GRP 16

__device__ __forceinline__ void group_barrier(int g) {
    __threadfence();
    __syncthreads();
    if (threadIdx.x == 0) {
        volatile unsigned* genp = &g_ggen[g * 32];
        unsigned cur = *genp;
        unsigned old = atomicAdd(&g_gcnt[g * 32], 1u);
        if (old == GRP - 1) {
            g_gcnt[g * 32] = 0;
            __threadfence();
            atomicExch(&g_ggen[g * 32], cur + 1);
        } else {
            while (*genp == cur) { }
        }
        __threadfence();
    }
    __syncthreads();
}

__global__ void __launch_bounds__(256, 1)
recurrence_kernel(const __half* __restrict__ W,        // WhhT [H, H] fp16 hi
                  const float* __restrict__ prem,      // raw [B,T,H]
                  const float* __restrict__ bvec,      // b_h
                  const float* __restrict__ xn_arr,    // [B*T]
                  __half* __restrict__ hs,             // [B, H] fp16 hi
                  float* __restrict__ mh,              // [2][B][H] (x1024 scaled)
                  float* __restrict__ out)             // [B,H]
{
    constexpr int BCH = 8;                  // 8 chunks of 64 = 512 K-half
    constexpr int CHB = 128 * 128;          // bytes per resident-B chunk (128 rows x 128B)
    extern __shared__ char smem[];
    __shared__ float redbuf[12 * 8];
    uint32_t sbase = smem_u32(smem);
    uint32_t sBres = sbase;                 // 128 KB resident B
    uint32_t sA[2] = { sbase + BCH * CHB, sbase + BCH * CHB + 32 * 128 };

    int bid  = blockIdx.x;
    int y   = bid >> 4;                     // row band (32 rows)
    int rem = bid & 15;
    int x   = rem >> 1;                     // col tile (128 wide)
    int z   = rem & 1;                      // K half (512 wide)
    int tid  = threadIdx.x;
    int warp = tid >> 5;
    int lane = tid & 31;
    int wn = warp;                          // 8 warps across N: WARP_N = 16, NT8 = 2

    // resident B: rows [x*128, +128) of W, K [z*512, +512)
    {
        const __half* Wb = W + (size_t)(x * 128) * KR + (size_t)z * 512;
        for (int u = tid; u < BCH * 128 * 8; u += 256) {
            int c   = u / (128 * 8);
            int rm  = u - c * (128 * 8);
            int row = rm >> 3, ch = rm & 7;
            uint32_t phys = (uint32_t)(c * CHB + row * 128 + ((ch ^ (row & 7)) << 4));
            cpasync16(sBres + phys, Wb + (size_t)row * KR + c * 64 + ch * 8);
        }
        CP_COMMIT();
    }

    const __half* Abase = hs + (size_t)(y * 32) * KR;
    float* mhz = mh + (size_t)z * BB * HH;
    int koff0 = z * 512;

    float hn_loc[2] = { EPSF, EPSF };
    int b0 = y * 32 + rem * 2;              // step rows b0, b0+1 (inside band y)

    // bias (constant across steps) in registers
    float bv[4];
    #pragma unroll
    for (int j = 0; j < 4; j++) bv[j] = bvec[tid + j * 256];
    float s_b2t = 0.0f;
    #pragma unroll
    for (int j = 0; j < 4; j++) s_b2t += bv[j] * bv[j];

    auto loadA = [&](int st, int c) {       // A chunk: 32 rows x 64 k = 4KB
        #pragma unroll
        for (int u = tid; u < 32 * 8; u += 256) {
            int row = u >> 3, ch = u & 7;
            uint32_t phys = (uint32_t)(row * 128 + ((ch ^ (row & 7)) << 4));
            cpasync16(sA[st] + phys, Abase + (size_t)row * KR + koff0 + c * 64 + ch * 8);
        }
    };

    for (int t = 0; t < TT; t++) {
        // prefetch step-phase operands independent of mh (overlap with GEMM)
        float p2r[2][4], xnv[2];
        #pragma unroll
        for (int r = 0; r < 2; r++) {
            const float* pr = prem + ((size_t)(b0 + r) * TT + t) * HH;
            #pragma unroll
            for (int j = 0; j < 4; j++) p2r[r][j] = pr[tid + j * 256];
            xnv[r] = xn_arr[(size_t)(b0 + r) * TT + t];
        }

        // ===== GEMM phase: mh[z] tile (rows y*32..+32, cols x*128..+128) =====
        float acc[2][2][4];
        #pragma unroll
        for (int i = 0; i < 2; i++)
            #pragma unroll
            for (int j = 0; j < 2; j++)
                #pragma unroll
                for (int e = 0; e < 4; e++) acc[i][j][e] = 0.0f;

        loadA(0, 0);
        CP_COMMIT();
        for (int c = 0; c < BCH; c++) {
            if (c + 1 < BCH) loadA((c + 1) & 1, c + 1);
            CP_COMMIT();
            CP_WAIT1();
            __syncthreads();

            uint32_t a = sA[c & 1];
            uint32_t b = sBres + c * CHB;
            #pragma unroll
            for (int s = 0; s < 4; s++) {
                uint32_t af[2][4];
                #pragma unroll
                for (int i = 0; i < 2; i++) {
                    int row = i * 16 + (lane & 15);
                    int ch  = 2 * s + (lane >> 4);
                    ldsm_x4(af[i][0], af[i][1], af[i][2], af[i][3],
                            a + row * 128 + ((ch ^ (row & 7)) << 4));
                }
                uint32_t bfm[4];
                {
                    int row = wn * 16 + (lane & 7) + ((lane >> 4) << 3);
                    int ch  = 2 * s + ((lane >> 3) & 1);
                    ldsm_x4(bfm[0], bfm[1], bfm[2], bfm[3],
                            b + row * 128 + ((ch ^ (row & 7)) << 4));
                }
                #pragma unroll
                for (int i = 0; i < 2; i++)
                    #pragma unroll
                    for (int nj = 0; nj < 2; nj++)
                        mma_fp16(acc[i][nj][0], acc[i][nj][1], acc[i][nj][2], acc[i][nj][3],
                                 af[i][0], af[i][1], af[i][2], af[i][3],
                                 bfm[nj * 2], bfm[nj * 2 + 1]);
            }
            __syncthreads();
        }

        // epilogue -> mh[z] (x1024 scaled; step divides)
        {
            int g = lane >> 2, t4 = lane & 3;
            #pragma unroll
            for (int i = 0; i < 2; i++)
                #pragma unroll
                for (int nj = 0; nj < 2; nj++) {
                    size_t row0 = (size_t)(y * 32 + i * 16 + g);
                    size_t col  = (size_t)(x * 128 + wn * 16 + nj * 8 + 2 * t4);
                    *reinterpret_cast<float2*>(&mhz[row0 * HH + col]) =
                        make_float2(acc[i][nj][0], acc[i][nj][1]);
                    *reinterpret_cast<float2*>(&mhz[(row0 + 8) * HH + col]) =
                        make_float2(acc[i][nj][2], acc[i][nj][3]);
                }
        }
        group_barrier(y);

        // ===== STEP phase: rows b0, b0+1 — fused dual-row reductions =====
        float m2r[2][4];
        float vals[12];
        #pragma unroll
        for (int r = 0; r < 2; r++) {
            int b = b0 + r;
            float s_mx2 = 0, s_mxm = 0, s_mxb = 0, s_m2 = 0, s_mb = 0, s_b2 = 0;
            #pragma unroll
            for (int j = 0; j < 4; j++) {
                int e = tid + j * 256;
                float mv = (__ldcv(&mh[(size_t)b * HH + e])
                          + __ldcv(&mh[(size_t)BB * HH + (size_t)b * HH + e])) * ISC2;
                float pv = p2r[r][j];
                float bb = bv[j];
                m2r[r][j] = mv;
                s_mx2 += pv * pv;  s_mxm += pv * mv;  s_mxb += pv * bb;
                s_m2  += mv * mv;  s_mb  += mv * bb;  s_b2  += bb * bb;
            }
            vals[r * 6 + 0] = s_mx2; vals[r * 6 + 1] = s_mxm; vals[r * 6 + 2] = s_mxb;
            vals[r * 6 + 3] = s_m2;  vals[r * 6 + 4] = s_mb;  vals[r * 6 + 5] = s_b2;
        }
        block_reduce8<12>(vals, redbuf);

        float cpr[2], cmr[2], cbr[2], ggr[2];
        #pragma unroll
        for (int r = 0; r < 2; r++) {
            float mx2 = vals[r * 6 + 0], mxm = vals[r * 6 + 1], mxb = vals[r * 6 + 2];
            float m2  = vals[r * 6 + 3], mb  = vals[r * 6 + 4], b2  = vals[r * 6 + 5];

            float xn  = xnv[r];
            float mxn = fmaxf(sqrtf(mx2), EPSF);
            float fp  = tanhf(mxn / xn * artanh_clip(xn)) / mxn;
            float p2  = fp * fp * mx2;
            float pm  = fp * mxm;
            float pb  = fp * mxb;

            float hn  = hn_loc[r];
            float mhn = fmaxf(sqrtf(m2), EPSF);
            float fu  = tanhf(mhn / hn * artanh_clip(hn)) / mhn;
            float u2  = fu * fu * m2;
            float ub  = fu * mb;

            float den1 = fmaxf(1.0f + 2.0f * ub + u2 * b2, EPSF);
            float a1 = (1.0f + 2.0f * ub + b2) / den1;
            float c1 = (1.0f - u2) / den1;
            float hid2 = a1 * a1 * u2 + 2.0f * a1 * c1 * ub + c1 * c1 * b2;
            float ph   = a1 * fu * pm + c1 * pb;

            float den2 = fmaxf(1.0f + 2.0f * ph + p2 * hid2, EPSF);
            float q1 = (1.0f + 2.0f * ph + hid2) / den2;
            float q2 = (1.0f - p2) / den2;
            float s2 = q1 * q1 * p2 + q2 * q2 * hid2 + 2.0f * q1 * q2 * ph;
            float sn = fmaxf(sqrtf(s2), EPSF);
            ggr[r] = artanh_clip(sn) / sn;
            cpr[r] = q1 * fp;
            cmr[r] = q2 * a1 * fu;
            cbr[r] = q2 * c1;
        }

        float v2r[2][4];
        float vv2[2] = { 0.0f, 0.0f };
        #pragma unroll
        for (int r = 0; r < 2; r++) {
            #pragma unroll
            for (int j = 0; j < 4; j++) {
                float sv = cpr[r] * p2r[r][j] + cmr[r] * m2r[r][j] + cbr[r] * bv[j];
                float vv = tanhf(ggr[r] * sv);
                v2r[r][j] = vv; vv2[r] += vv * vv;
            }
        }
        block_reduce8<2>(vv2, redbuf);

        #pragma unroll
        for (int r = 0; r < 2; r++) {
            int b = b0 + r;
            float vn = fmaxf(sqrtf(vv2[r]), EPSF);
            float kk = tanhf(vn) / vn;
            __half* hrow = hs + (size_t)b * KR;
            float* orow = out + (size_t)b * HH;
            #pragma unroll
            for (int j = 0; j < 4; j++) {
                int e = tid + j * 256;
                float hv = kk * v2r[r][j];
                hrow[e] = __float2half_rn(hv * XSC);
                if (t == TT - 1) orow[e] = hv;
            }
            hn_loc[r] = fmaxf(tanhf(vn), EPSF);
        }
        group_barrier(y);
    }
}

// ---------------- launch ----------------
extern "C" void kernel_launch(void* const* d_in, const int* in_sizes, int n_in,
                              void* d_out, int out_size)
{
    const float* inp  = (const float*)d_in[0];   // [B,T,E]
    const float* W_ih = (const float*)d_in[1];   // [E,H]
    const float* W_hh = (const float*)d_in[2];   // [H,H]
    const float* b_h  = (const float*)d_in[3];   // [H]
    float* out = (float*)d_out;                  // [B,H]

    __half *Xs, *WihT, *WhhT, *hs;
    float *prem, *mh, *xn;
    cudaGetSymbolAddress((void**)&Xs,   g_Xs);
    cudaGetSymbolAddress((void**)&WihT, g_WihT);
    cudaGetSymbolAddress((void**)&WhhT, g_WhhT);
    cudaGetSymbolAddress((void**)&hs,   g_hs);
    cudaGetSymbolAddress((void**)&prem, g_prem);
    cudaGetSymbolAddress((void**)&mh,   g_mh);
    cudaGetSymbolAddress((void**)&xn,   g_xn);

    const int SMEM_BIG = 3 * (128 + 128) * 128;            // 96 KB (3 stages)
    const int SMEM_REC = 8 * 128 * 128 + 2 * 32 * 128;     // 128KB + 8KB = 136 KB
    cudaFuncSetAttribute(big_gemm_kernel,
                         cudaFuncAttributeMaxDynamicSharedMemorySize, SMEM_BIG);
    cudaFuncSetAttribute(recurrence_kernel,
                         cudaFuncAttributeMaxDynamicSharedMemorySize, SMEM_REC);

    // init hidden = 0
    {
        int n = (int)((size_t)BB * KR / 2);
        init_kernel<<<(n + 255) / 256, 256>>>((uint32_t*)hs);
    }

    // prep: weight splits + X split/norms
    {
        dim3 gw(HH / 32, HH / 32);
        splitWih_kernel<<<gw, 256>>>(W_ih, WihT);
        splitWhh_kernel<<<gw, 256>>>(W_hh, WhhT);
        splitX_kernel<<<BB * TT, 256>>>(inp, Xs, xn);
    }

    // big GEMM: raw prem = Xs @ WihT^T  [32768, 1024] (fp16 2-seg)
    {
        dim3 grid(HH / 128, (BB * TT) / 128);
        big_gemm_kernel<<<grid, 256, SMEM_BIG>>>(Xs, WihT, prem);
    }

    // persistent recurrence: one kernel for all 128 steps
    recurrence_kernel<<<128, 256, SMEM_REC>>>(WhhT, prem, b_h, xn, hs, mh, out);
}

// round 14
// speedup vs baseline: 1.7163x; 1.1488x over previous
#include <cuda_runtime.h>
#include <cuda_bf16.h>
#include <cuda_fp16.h>
#include <math.h>
#include <stdint.h>

// ---------------- problem constants ----------------
#define BB   256      // batch
#define TT   128      // time steps
#define EE   1024     // input dim
#define HH   1024     // hidden dim
#define KB1  1024     // big-GEMM K (X hi-only fp16)
#define KR   1024     // recurrence K (h hi-only fp16)
#define EPSF 1e-6f
#define XSC  32.0f    // pre-scale per side for fp16 (product /1024)
#define ISC2 (1.0f / (XSC * XSC))

// ---------------- scratch ----------------
__device__ __half g_Xs   [(size_t)BB * TT * KB1]; // X fp16 hi [B*T, E], x*32
__device__ __half g_WihT [(size_t)HH * KB1];      // W_ih^T fp16 hi [H, E], W*32
__device__ __half g_WhhT [(size_t)HH * KR];       // W_hh^T fp16 hi [H, H], W*32
__device__ __half g_hs   [(size_t)BB * KR];       // h fp16 hi [B, H], h*32
__device__ float g_prem[(size_t)BB * TT * HH];    // RAW X@W_ih (true scale), all t
__device__ float g_mh  [2 * (size_t)BB * HH];     // 2 split-K partials (scaled x1024)
__device__ float g_xn  [(size_t)BB * TT];         // ||x_t|| per row (clamped)
// per-group barriers (8 groups, cache-line separated)
__device__ unsigned g_gcnt[8 * 32];
__device__ unsigned g_ggen[8 * 32];

// ---------------- PTX helpers (sm_80-level) ----------------
__device__ __forceinline__ uint32_t smem_u32(const void* p) {
    uint32_t a;
    asm("{ .reg .u64 t; cvta.to.shared.u64 t, %1; cvt.u32.u64 %0, t; }" : "=r"(a) : "l"(p));
    return a;
}
__device__ __forceinline__ void cpasync16(uint32_t s, const void* g) {
    asm volatile("cp.async.cg.shared.global [%0], [%1], 16;" :: "r"(s), "l"(g));
}
#define CP_COMMIT() asm volatile("cp.async.commit_group;" ::: "memory")
#define CP_WAIT0()  asm volatile("cp.async.wait_group 0;" ::: "memory")
#define CP_WAIT2()  asm volatile("cp.async.wait_group 2;" ::: "memory")

__device__ __forceinline__ void ldsm_x4(uint32_t& r0, uint32_t& r1, uint32_t& r2, uint32_t& r3,
                                        uint32_t addr) {
    asm volatile("ldmatrix.sync.aligned.m8n8.x4.shared.b16 {%0,%1,%2,%3}, [%4];"
                 : "=r"(r0), "=r"(r1), "=r"(r2), "=r"(r3) : "r"(addr));
}
__device__ __forceinline__ void mma_fp16(float& d0, float& d1, float& d2, float& d3,
                                         uint32_t a0, uint32_t a1, uint32_t a2, uint32_t a3,
                                         uint32_t b0, uint32_t b1) {
    asm volatile(
        "mma.sync.aligned.m16n8k16.row.col.f32.f16.f16.f32 "
        "{%0,%1,%2,%3}, {%4,%5,%6,%7}, {%8,%9}, {%0,%1,%2,%3};"
        : "+f"(d0), "+f"(d1), "+f"(d2), "+f"(d3)
        : "r"(a0), "r"(a1), "r"(a2), "r"(a3), "r"(b0), "r"(b1));
}

// ---------------- init ----------------
__global__ void init_kernel(uint32_t* hs_u32) {
    int i = blockIdx.x * blockDim.x + threadIdx.x;
    if (i < (int)((size_t)BB * KR / 2)) hs_u32[i] = 0u;
}

// ---------------- splitX: fp16 hi of 32*x, plus ||x|| ----------------
__global__ __launch_bounds__(256) void splitX_kernel(const float* __restrict__ X,
                                                     __half* __restrict__ Xs,
                                                     float* __restrict__ xn) {
    __shared__ float sh[8];
    size_t r = blockIdx.x;
    const float* x = X + r * EE;
    __half* row = Xs + r * KB1;
    float x2 = 0.0f;
    #pragma unroll
    for (int j = 0; j < 4; j++) {
        int e = threadIdx.x + j * 256;
        float v = x[e];
        x2 += v * v;
        row[e] = __float2half_rn(v * XSC);
    }
    #pragma unroll
    for (int o = 16; o > 0; o >>= 1) x2 += __shfl_down_sync(0xffffffffu, x2, o);
    if ((threadIdx.x & 31) == 0) sh[threadIdx.x >> 5] = x2;
    __syncthreads();
    if (threadIdx.x == 0) {
        float s = 0.0f;
        #pragma unroll
        for (int w = 0; w < 8; w++) s += sh[w];
        xn[r] = fmaxf(sqrtf(s), EPSF);
    }
}

// ---------------- W [K,N] -> fp16 Wt [N, K] hi, scaled, transposed ----------
__global__ __launch_bounds__(256) void splitW_kernel(const float* __restrict__ W,
                                                     __half* __restrict__ Wt) {
    __shared__ float tile[32][33];
    int n0 = blockIdx.x * 32;
    int k0 = blockIdx.y * 32;
    int tx = threadIdx.x & 31;
    int ty = threadIdx.x >> 5;
    #pragma unroll
    for (int i = 0; i < 32; i += 8)
        tile[ty + i][tx] = W[(size_t)(k0 + ty + i) * HH + n0 + tx];
    __syncthreads();
    #pragma unroll
    for (int i = 0; i < 32; i += 8) {
        float v = tile[tx][ty + i] * XSC;
        int n = n0 + ty + i;
        int k = k0 + tx;
        Wt[(size_t)n * KB1 + k] = __float2half_rn(v);
    }
}

// ---------------- big GEMM (fp16 hi-only): prem_raw = Xs @ WihT^T / 1024 ------
__global__ void __launch_bounds__(256, 2)
big_gemm_kernel(const __half* __restrict__ A,
                const __half* __restrict__ B,
                float* __restrict__ C)
{
    constexpr int ABYTES = 128 * 128, BBYTES = 128 * 128;
    constexpr int NCH = KB1 / 64;     // 16
    extern __shared__ char smem[];
    uint32_t sbase = smem_u32(smem);
    uint32_t sA[3], sB[3];
    #pragma unroll
    for (int s = 0; s < 3; s++) {
        sA[s] = sbase + s * (ABYTES + BBYTES);
        sB[s] = sA[s] + ABYTES;
    }

    int tid  = threadIdx.x;
    int warp = tid >> 5;
    int lane = tid & 31;
    int wm = warp & 1;
    int wn = warp >> 1;

    size_t rowTile = (size_t)blockIdx.y * 128;
    size_t colTile = (size_t)blockIdx.x * 128;
    const __half* Abase = A + rowTile * KB1;
    const __half* Bbase = B + colTile * KB1;

    float acc[4][4][4];
    #pragma unroll
    for (int i = 0; i < 4; i++)
        #pragma unroll
        for (int j = 0; j < 4; j++)
            #pragma unroll
            for (int e = 0; e < 4; e++) acc[i][j][e] = 0.0f;

    auto load_stage = [&](int st, int c) {
        const __half* Ag = Abase + (size_t)c * 64;
        const __half* Bg = Bbase + (size_t)c * 64;
        #pragma unroll
        for (int u = tid; u < 128 * 8; u += 256) {
            int row = u >> 3, ch = u & 7;
            uint32_t phys = (uint32_t)(row * 128 + ((ch ^ (row & 7)) << 4));
            cpasync16(sA[st] + phys, Ag + (size_t)row * KB1 + ch * 8);
        }
        #pragma unroll
        for (int u = tid; u < 128 * 8; u += 256) {
            int row = u >> 3, ch = u & 7;
            uint32_t phys = (uint32_t)(row * 128 + ((ch ^ (row & 7)) << 4));
            cpasync16(sB[st] + phys, Bg + (size_t)row * KB1 + ch * 8);
        }
    };

    load_stage(0, 0); CP_COMMIT();
    load_stage(1, 1); CP_COMMIT();

    int st = 0;
    for (int c = 0; c < NCH; c++) {
        if (c + 2 < NCH) load_stage((st + 2) % 3, c + 2);
        CP_COMMIT();
        CP_WAIT2();
        __syncthreads();

        uint32_t a = sA[st], b = sB[st];
        #pragma unroll
        for (int s = 0; s < 4; s++) {
            uint32_t af[4][4];
            #pragma unroll
            for (int i = 0; i < 4; i++) {
                int row = wm * 64 + i * 16 + (lane & 15);
                int ch  = 2 * s + (lane >> 4);
                ldsm_x4(af[i][0], af[i][1], af[i][2], af[i][3],
                        a + row * 128 + ((ch ^ (row & 7)) << 4));
            }
            uint32_t bfm[2][4];
            #pragma unroll
            for (int j = 0; j < 2; j++) {
                int row = wn * 32 + j * 16 + (lane & 7) + ((lane >> 4) << 3);
                int ch  = 2 * s + ((lane >> 3) & 1);
                ldsm_x4(bfm[j][0], bfm[j][1], bfm[j][2], bfm[j][3],
                        b + row * 128 + ((ch ^ (row & 7)) << 4));
            }
            #pragma unroll
            for (int i = 0; i < 4; i++)
                #pragma unroll
                for (int nj = 0; nj < 4; nj++)
                    mma_fp16(acc[i][nj][0], acc[i][nj][1], acc[i][nj][2], acc[i][nj][3],
                             af[i][0], af[i][1], af[i][2], af[i][3],
                             bfm[nj >> 1][(nj & 1) * 2], bfm[nj >> 1][(nj & 1) * 2 + 1]);
        }
        __syncthreads();
        st = (st + 1) % 3;
    }

    int g = lane >> 2, t4 = lane & 3;
    #pragma unroll
    for (int i = 0; i < 4; i++)
        #pragma unroll
        for (int nj = 0; nj < 4; nj++) {
            size_t row0 = rowTile + wm * 64 + i * 16 + g;
            size_t col  = colTile + wn * 32 + nj * 8 + 2 * t4;
            *reinterpret_cast<float2*>(&C[row0 * HH + col]) =
                make_float2(acc[i][nj][0] * ISC2, acc[i][nj][1] * ISC2);
            *reinterpret_cast<float2*>(&C[(row0 + 8) * HH + col]) =
                make_float2(acc[i][nj][2] * ISC2, acc[i][nj][3] * ISC2);
        }
}

// ---------------- helpers for step math ----------------
template <int NV>
__device__ __forceinline__ void block_reduce8(float* vals, float* shbuf /* NV*8 */) {
    __syncthreads();
    #pragma unroll
    for (int v = 0; v < NV; v++) {
        float x = vals[v];
        #pragma unroll
        for (int o = 16; o > 0; o >>= 1) x += __shfl_down_sync(0xffffffffu, x, o);
        if ((threadIdx.x & 31) == 0) shbuf[v * 8 + (threadIdx.x >> 5)] = x;
    }
    __syncthreads();
    #pragma unroll
    for (int v = 0; v < NV; v++) {
        float s = 0.0f;
        #pragma unroll
        for (int w = 0; w < 8; w++) s += shbuf[v * 8 + w];
        vals[v] = s;
    }
}
__device__ __forceinline__ float artanh_clip(float x) {
    return atanhf(fminf(x, 1.0f - 1e-6f));
}

// ---------------- persistent recurrence kernel (256 thr, 128 CTAs) ----------
// Grid decode: y = bid>>4 (row band of 32), rem = bid&15, x = rem>>1 (col tile
// of 128), z = rem&1 (K half of 512). Only the 16 CTAs of a y-group couple.
#define GRP 16

__device__ __forceinline__ void group_barrier(int g) {
    __threadfence();
    __syncthreads();
    if (threadIdx.x == 0) {
        volatile unsigned* genp = &g_ggen[g * 32];
        unsigned cur = *genp;
        unsigned old = atomicAdd(&g_gcnt[g * 32], 1u);
        if (old == GRP - 1) {
            g_gcnt[g * 32] = 0;
            __threadfence();
            atomicExch(&g_ggen[g * 32], cur + 1);
        } else {
            while (*genp == cur) { }
        }
        __threadfence();
    }
    __syncthreads();
}

__global__ void __launch_bounds__(256, 1)
recurrence_kernel(const __half* __restrict__ W,        // WhhT [H, H] fp16 hi
                  const float* __restrict__ prem,      // raw [B,T,H]
                  const float* __restrict__ bvec,      // b_h
                  const float* __restrict__ xn_arr,    // [B*T]
                  __half* __restrict__ hs,             // [B, H] fp16 hi
                  float* __restrict__ mh,              // [2][B][H] (x1024 scaled)
                  float* __restrict__ out)             // [B,H]
{
    constexpr int BCH = 8;                  // 8 chunks of 64 = 512 K-half
    constexpr int CHB = 128 * 128;          // bytes per resident-B chunk (128 rows x 128B)
    constexpr int ACH = 32 * 128;           // bytes per A chunk (32 rows x 128B)
    extern __shared__ char smem[];
    __shared__ float redbuf[12 * 8];
    uint32_t sbase = smem_u32(smem);
    uint32_t sBres = sbase;                 // 128 KB resident B
    uint32_t sAt   = sbase + BCH * CHB;     // 32 KB whole A tile (8 chunks)

    int bid  = blockIdx.x;
    int y   = bid >> 4;                     // row band (32 rows)
    int rem = bid & 15;
    int x   = rem >> 1;                     // col tile (128 wide)
    int z   = rem & 1;                      // K half (512 wide)
    int tid  = threadIdx.x;
    int warp = tid >> 5;
    int lane = tid & 31;
    int wn = warp;                          // 8 warps across N: WARP_N = 16, NT8 = 2

    // resident B: rows [x*128, +128) of W, K [z*512, +512)
    {
        const __half* Wb = W + (size_t)(x * 128) * KR + (size_t)z * 512;
        for (int u = tid; u < BCH * 128 * 8; u += 256) {
            int c   = u / (128 * 8);
            int rm  = u - c * (128 * 8);
            int row = rm >> 3, ch = rm & 7;
            uint32_t phys = (uint32_t)(c * CHB + row * 128 + ((ch ^ (row & 7)) << 4));
            cpasync16(sBres + phys, Wb + (size_t)row * KR + c * 64 + ch * 8);
        }
        CP_COMMIT();
    }

    const __half* Abase = hs + (size_t)(y * 32) * KR;
    float* mhz = mh + (size_t)z * BB * HH;
    int koff0 = z * 512;

    float hn_loc[2] = { EPSF, EPSF };
    int b0 = y * 32 + rem * 2;              // step rows b0, b0+1 (inside band y)

    // bias (constant across steps) in registers
    float bv[4];
    #pragma unroll
    for (int j = 0; j < 4; j++) bv[j] = bvec[tid + j * 256];

    for (int t = 0; t < TT; t++) {
        // load WHOLE A tile (32 rows x 512 k = 32 KB) in one burst
        #pragma unroll
        for (int u = tid; u < BCH * 32 * 8; u += 256) {
            int c   = u >> 8;               // /(32*8)
            int rm  = u & 255;
            int row = rm >> 3, ch = rm & 7;
            uint32_t phys = (uint32_t)(c * ACH + row * 128 + ((ch ^ (row & 7)) << 4));
            cpasync16(sAt + phys, Abase + (size_t)row * KR + koff0 + c * 64 + ch * 8);
        }
        CP_COMMIT();

        // prefetch step-phase operands independent of mh (overlap with A load)
        float p2r[2][4], xnv[2];
        #pragma unroll
        for (int r = 0; r < 2; r++) {
            const float* pr = prem + ((size_t)(b0 + r) * TT + t) * HH;
            #pragma unroll
            for (int j = 0; j < 4; j++) p2r[r][j] = pr[tid + j * 256];
            xnv[r] = xn_arr[(size_t)(b0 + r) * TT + t];
        }

        // ===== GEMM phase: mh[z] tile (rows y*32..+32, cols x*128..+128) =====
        float acc[2][2][4];
        #pragma unroll
        for (int i = 0; i < 2; i++)
            #pragma unroll
            for (int j = 0; j < 2; j++)
                #pragma unroll
                for (int e = 0; e < 4; e++) acc[i][j][e] = 0.0f;

        CP_WAIT0();
        __syncthreads();

        #pragma unroll
        for (int c = 0; c < BCH; c++) {
            uint32_t a = sAt + c * ACH;
            uint32_t b = sBres + c * CHB;
            #pragma unroll
            for (int s = 0; s < 4; s++) {
                uint32_t af[2][4];
                #pragma unroll
                for (int i = 0; i < 2; i++) {
                    int row = i * 16 + (lane & 15);
                    int ch  = 2 * s + (lane >> 4);
                    ldsm_x4(af[i][0], af[i][1], af[i][2], af[i][3],
                            a + row * 128 + ((ch ^ (row & 7)) << 4));
                }
                uint32_t bfm[4];
                {
                    int row = wn * 16 + (lane & 7) + ((lane >> 4) << 3);
                    int ch  = 2 * s + ((lane >> 3) & 1);
                    ldsm_x4(bfm[0], bfm[1], bfm[2], bfm[3],
                            b + row * 128 + ((ch ^ (row & 7)) << 4));
                }
                #pragma unroll
                for (int i = 0; i < 2; i++)
                    #pragma unroll
                    for (int nj = 0; nj < 2; nj++)
                        mma_fp16(acc[i][nj][0], acc[i][nj][1], acc[i][nj][2], acc[i][nj][3],
                                 af[i][0], af[i][1], af[i][2], af[i][3],
                                 bfm[nj * 2], bfm[nj * 2 + 1]);
            }
        }

        // epilogue -> mh[z] (x1024 scaled; step divides)
        {
            int g = lane >> 2, t4 = lane & 3;
            #pragma unroll
            for (int i = 0; i < 2; i++)
                #pragma unroll
                for (int nj = 0; nj < 2; nj++) {
                    size_t row0 = (size_t)(y * 32 + i * 16 + g);
                    size_t col  = (size_t)(x * 128 + wn * 16 + nj * 8 + 2 * t4);
                    *reinterpret_cast<float2*>(&mhz[row0 * HH + col]) =
                        make_float2(acc[i][nj][0], acc[i][nj][1]);
                    *reinterpret_cast<float2*>(&mhz[(row0 + 8) * HH + col]) =
                        make_float2(acc[i][nj][2], acc[i][nj][3]);
                }
        }
        group_barrier(y);

        // ===== STEP phase: rows b0, b0+1 — fused dual-row reductions =====
        float m2r[2][4];
        float vals[12];
        #pragma unroll
        for (int r = 0; r < 2; r++) {
            int b = b0 + r;
            float s_mx2 = 0, s_mxm = 0, s_mxb = 0, s_m2 = 0, s_mb = 0, s_b2 = 0;
            #pragma unroll
            for (int j = 0; j < 4; j++) {
                int e = tid + j * 256;
                float mv = (__ldcv(&mh[(size_t)b * HH + e])
                          + __ldcv(&mh[(size_t)BB * HH + (size_t)b * HH + e])) * ISC2;
                float pv = p2r[r][j];
                float bb = bv[j];
                m2r[r][j] = mv;
                s_mx2 += pv * pv;  s_mxm += pv * mv;  s_mxb += pv * bb;
                s_m2  += mv * mv;  s_mb  += mv * bb;  s_b2  += bb * bb;
            }
            vals[r * 6 + 0] = s_mx2; vals[r * 6 + 1] = s_mxm; vals[r * 6 + 2] = s_mxb;
            vals[r * 6 + 3] = s_m2;  vals[r * 6 + 4] = s_mb;  vals[r * 6 + 5] = s_b2;
        }
        block_reduce8<12>(vals, redbuf);

        float cpr[2], cmr[2], cbr[2], ggr[2];
        #pragma unroll
        for (int r = 0; r < 2; r++) {
            float mx2 = vals[r * 6 + 0], mxm = vals[r * 6 + 1], mxb = vals[r * 6 + 2];
            float m2  = vals[r * 6 + 3], mb  = vals[r * 6 + 4], b2  = vals[r * 6 + 5];

            float xn  = xnv[r];
            float mxn = fmaxf(sqrtf(mx2), EPSF);
            float fp  = tanhf(mxn / xn * artanh_clip(xn)) / mxn;
            float p2  = fp * fp * mx2;
            float pm  = fp * mxm;
            float pb  = fp * mxb;

            float hn  = hn_loc[r];
            float mhn = fmaxf(sqrtf(m2), EPSF);
            float fu  = tanhf(mhn / hn * artanh_clip(hn)) / mhn;
            float u2  = fu * fu * m2;
            float ub  = fu * mb;

            float den1 = fmaxf(1.0f + 2.0f * ub + u2 * b2, EPSF);
            float a1 = (1.0f + 2.0f * ub + b2) / den1;
            float c1 = (1.0f - u2) / den1;
            float hid2 = a1 * a1 * u2 + 2.0f * a1 * c1 * ub + c1 * c1 * b2;
            float ph   = a1 * fu * pm + c1 * pb;

            float den2 = fmaxf(1.0f + 2.0f * ph + p2 * hid2, EPSF);
            float q1 = (1.0f + 2.0f * ph + hid2) / den2;
            float q2 = (1.0f - p2) / den2;
            float s2 = q1 * q1 * p2 + q2 * q2 * hid2 + 2.0f * q1 * q2 * ph;
            float sn = fmaxf(sqrtf(s2), EPSF);
            ggr[r] = artanh_clip(sn) / sn;
            cpr[r] = q1 * fp;
            cmr[r] = q2 * a1 * fu;
            cbr[r] = q2 * c1;
        }

        float v2r[2][4];
        float vv2[2] = { 0.0f, 0.0f };
        #pragma unroll
        for (int r = 0; r < 2; r++) {
            #pragma unroll
            for (int j = 0; j < 4; j++) {
                float sv = cpr[r] * p2r[r][j] + cmr[r] * m2r[r][j] + cbr[r] * bv[j];
                float vv = tanhf(ggr[r] * sv);
                v2r[r][j] = vv; vv2[r] += vv * vv;
            }
        }
        block_reduce8<2>(vv2, redbuf);

        #pragma unroll
        for (int r = 0; r < 2; r++) {
            int b = b0 + r;
            float vn = fmaxf(sqrtf(vv2[r]), EPSF);
            float kk = tanhf(vn) / vn;
            __half* hrow = hs + (size_t)b * KR;
            float* orow = out + (size_t)b * HH;
            #pragma unroll
            for (int j = 0; j < 4; j++) {
                int e = tid + j * 256;
                float hv = kk * v2r[r][j];
                hrow[e] = __float2half_rn(hv * XSC);
                if (t == TT - 1) orow[e] = hv;
            }
            hn_loc[r] = fmaxf(tanhf(vn), EPSF);
        }
        group_barrier(y);
    }
}

// ---------------- launch ----------------
extern "C" void kernel_launch(void* const* d_in, const int* in_sizes, int n_in,
                              void* d_out, int out_size)
{
    const float* inp  = (const float*)d_in[0];   // [B,T,E]
    const float* W_ih = (const float*)d_in[1];   // [E,H]
    const float* W_hh = (const float*)d_in[2];   // [H,H]
    const float* b_h  = (const float*)d_in[3];   // [H]
    float* out = (float*)d_out;                  // [B,H]

    __half *Xs, *WihT, *WhhT, *hs;
    float *prem, *mh, *xn;
    cudaGetSymbolAddress((void**)&Xs,   g_Xs);
    cudaGetSymbolAddress((void**)&WihT, g_WihT);
    cudaGetSymbolAddress((void**)&WhhT, g_WhhT);
    cudaGetSymbolAddress((void**)&hs,   g_hs);
    cudaGetSymbolAddress((void**)&prem, g_prem);
    cudaGetSymbolAddress((void**)&mh,   g_mh);
    cudaGetSymbolAddress((void**)&xn,   g_xn);

    const int SMEM_BIG = 3 * (128 + 128) * 128;            // 96 KB (3 stages)
    const int SMEM_REC = 8 * 128 * 128 + 8 * 32 * 128;     // 128KB + 32KB = 160 KB
    cudaFuncSetAttribute(big_gemm_kernel,
                         cudaFuncAttributeMaxDynamicSharedMemorySize, SMEM_BIG);
    cudaFuncSetAttribute(recurrence_kernel,
                         cudaFuncAttributeMaxDynamicSharedMemorySize, SMEM_REC);

    // init hidden = 0
    {
        int n = (int)((size_t)BB * KR / 2);
        init_kernel<<<(n + 255) / 256, 256>>>((uint32_t*)hs);
    }

    // prep: weight transposes + X scale/norms (all hi-only fp16)
    {
        dim3 gw(HH / 32, HH / 32);
        splitW_kernel<<<gw, 256>>>(W_ih, WihT);
        splitW_kernel<<<gw, 256>>>(W_hh, WhhT);
        splitX_kernel<<<BB * TT, 256>>>(inp, Xs, xn);
    }

    // big GEMM: raw prem = Xs @ WihT^T  [32768, 1024], K=1024
    {
        dim3 grid(HH / 128, (BB * TT) / 128);
        big_gemm_kernel<<<grid, 256, SMEM_BIG>>>(Xs, WihT, prem);
    }

    // persistent recurrence: one kernel for all 128 steps
    recurrence_kernel<<<128, 256, SMEM_REC>>>(WhhT, prem, b_h, xn, hs, mh, out);
}